// round 4
// baseline (speedup 1.0000x reference)
#include <cuda_runtime.h>
#include <cuda_fp16.h>
#include <math.h>

#define NN    50000
#define NE    800000
#define F1    128
#define H     64
#define NCLS  40
#define NPAD  50176       // multiple of 64

__device__ float  g_A1[(size_t)NPAD * 64];     // layer-1 message accumulator
__device__ float  g_A2[(size_t)NPAD * 40];     // layer-2 message accumulator
__device__ float  g_deg[NPAD];
__device__ __half g_y16[(size_t)NPAD * 128];   // [ x@W0 | x@(W1-W0) ] fp16
__device__ float  g_yroot[(size_t)NPAD * 64];  // x@root1 fp32
__device__ __half g_z16[(size_t)NPAD * 80];    // [ h@W0' | h@(W1'-W0') ] fp16
__device__ float  g_zroot[(size_t)NPAD * 40];  // h@root2 fp32

// ---------------------------------------------------------------------------
__device__ __forceinline__ void red_add_v4(float* addr, float a, float b, float c, float d) {
    asm volatile("red.global.add.v4.f32 [%0], {%1,%2,%3,%4};"
                 :: "l"(addr), "f"(a), "f"(b), "f"(c), "f"(d) : "memory");
}

__device__ __forceinline__ void h8_to_f8(int4 p, float* f) {
    const __half2* h = reinterpret_cast<const __half2*>(&p);
    #pragma unroll
    for (int q = 0; q < 4; q++) {
        float2 t = __half22float2(h[q]);
        f[2 * q] = t.x; f[2 * q + 1] = t.y;
    }
}

// ---------------------------------------------------------------------------
// proj1: y[n] = x[n] @ [W0 | W1-W0 | root1]  (K=128, 192 outs split over grid.y)
// Also zeros A1 + deg for its node rows (grid.y==0 only).
__global__ __launch_bounds__(256) void proj1_kernel(
    const float* __restrict__ x,
    const float* __restrict__ W1,
    const float* __restrict__ root1)
{
    extern __shared__ float smem[];
    float* sw = smem;               // [128][96]
    float* sx = smem + 128 * 96;    // [64][36]
    int tid = threadIdx.x;
    int ob = blockIdx.y * 96;
    int nb = blockIdx.x * 64;

    if (blockIdx.y == 0) {          // zero A1 rows + deg for this node tile
        float4 z4 = make_float4(0.f, 0.f, 0.f, 0.f);
        float4* a = reinterpret_cast<float4*>(g_A1 + (size_t)nb * 64);
        for (int i = tid; i < 1024; i += 256) a[i] = z4;
        if (tid < 64) g_deg[nb + tid] = 0.f;
    }

    for (int idx = tid; idx < 128 * 96; idx += 256) {
        int k = idx / 96, oc = idx % 96, o = ob + oc;
        float val;
        if (o < 64)       val = W1[k * 64 + o];
        else if (o < 128) { int oo = o - 64; val = W1[128 * 64 + k * 64 + oo] - W1[k * 64 + oo]; }
        else              val = root1[k * 64 + (o - 128)];
        sw[idx] = val;
    }

    int og = tid & 15;   // 16 groups x 6 outs
    int ng = tid >> 4;   // 16 groups x 4 nodes
    float acc[4][6] = {};

    for (int kk = 0; kk < 128; kk += 32) {
        __syncthreads();
        #pragma unroll
        for (int r = 0; r < 2; r++) {
            int i = tid * 2 + r;
            int row = i >> 3, c = i & 7;
            int n = nb + row; if (n > NN - 1) n = NN - 1;
            float4 xv = __ldg(reinterpret_cast<const float4*>(x + (size_t)n * F1 + kk) + c);
            *reinterpret_cast<float4*>(sx + row * 36 + c * 4) = xv;
        }
        __syncthreads();
        #pragma unroll
        for (int k2 = 0; k2 < 32; k2++) {
            int kg = kk + k2;
            float w[6];
            *reinterpret_cast<float2*>(w + 0) = *reinterpret_cast<float2*>(sw + kg * 96 + og * 6);
            *reinterpret_cast<float2*>(w + 2) = *reinterpret_cast<float2*>(sw + kg * 96 + og * 6 + 2);
            *reinterpret_cast<float2*>(w + 4) = *reinterpret_cast<float2*>(sw + kg * 96 + og * 6 + 4);
            #pragma unroll
            for (int i = 0; i < 4; i++) {
                float xr = sx[(ng * 4 + i) * 36 + k2];
                #pragma unroll
                for (int j = 0; j < 6; j++) acc[i][j] += xr * w[j];
            }
        }
    }

    #pragma unroll
    for (int i = 0; i < 4; i++) {
        int n = nb + ng * 4 + i;
        #pragma unroll
        for (int j = 0; j < 6; j++) {
            int o = ob + og * 6 + j;
            if (o < 128) g_y16[(size_t)n * 128 + o] = __float2half_rn(acc[i][j]);
            else         g_yroot[(size_t)n * 64 + (o - 128)] = acc[i][j];
        }
    }
}

// ---------------------------------------------------------------------------
// scatter1: A1[dst] += y0[src] + v*yd[src] (fp16 gather, fp32 RED); deg[dst]++.
// 8 lanes/edge, each lane handles 8 halves (one int4).
__global__ __launch_bounds__(256) void scatter1_kernel(
    const int* __restrict__ src,
    const int* __restrict__ dst,
    const float* __restrict__ ea)
{
    int t = blockIdx.x * 256 + threadIdx.x;
    int e = t >> 3;
    int lane = t & 7;
    int lid = threadIdx.x & 31;
    int s = 0, d = 0; float v = 0.f;
    if ((lid & 7) == 0) {
        s = __ldg(src + e); d = __ldg(dst + e); v = __ldg(ea + e);
    }
    int srcLane = lid & 24;
    s = __shfl_sync(0xffffffffu, s, srcLane);
    d = __shfl_sync(0xffffffffu, d, srcLane);
    v = __shfl_sync(0xffffffffu, v, srcLane);

    const int4* yr = reinterpret_cast<const int4*>(g_y16 + (size_t)s * 128);
    int4 p0 = __ldg(yr + lane);
    int4 pd = __ldg(yr + 8 + lane);
    float a0[8], ad[8];
    h8_to_f8(p0, a0);
    h8_to_f8(pd, ad);
    float m[8];
    #pragma unroll
    for (int q = 0; q < 8; q++) m[q] = fmaf(v, ad[q], a0[q]);
    float* Ap = g_A1 + (size_t)d * 64 + lane * 8;
    red_add_v4(Ap,     m[0], m[1], m[2], m[3]);
    red_add_v4(Ap + 4, m[4], m[5], m[6], m[7]);
    if (lane == 0) atomicAdd(g_deg + d, 1.0f);
}

// ---------------------------------------------------------------------------
// proj2 (fused elu): h = elu(A1/deg + yroot + bias1) computed into SMEM,
// then z[n] = h[n] @ [W0' | W1'-W0' | root2 | 0]  (K=64, 128 outs, one block).
// Also zeros A2 for its node rows.
__global__ __launch_bounds__(256) void proj2_kernel(
    const float* __restrict__ W2,
    const float* __restrict__ root2,
    const float* __restrict__ bias1)
{
    extern __shared__ float smem[];
    float* sw = smem;               // [64][128]
    float* sh = smem + 64 * 128;    // [64][65]
    __shared__ float sinv[64];
    __shared__ float sb[64];
    int tid = threadIdx.x;
    int nb = blockIdx.x * 64;

    {   // zero A2 rows for this tile
        float4 z4 = make_float4(0.f, 0.f, 0.f, 0.f);
        float4* a = reinterpret_cast<float4*>(g_A2 + (size_t)nb * 40);
        for (int i = tid; i < 640; i += 256) a[i] = z4;
    }
    if (tid < 64) {
        sb[tid] = __ldg(bias1 + tid);
        sinv[tid] = 1.0f / fmaxf(g_deg[nb + tid], 1.0f);
    }

    for (int idx = tid; idx < 64 * 128; idx += 256) {
        int k = idx >> 7, o = idx & 127;
        float val;
        if (o < 40)       val = W2[k * 40 + o];
        else if (o < 80)  { int oo = o - 40; val = W2[64 * 40 + k * 40 + oo] - W2[k * 40 + oo]; }
        else if (o < 120) val = root2[k * 40 + (o - 80)];
        else              val = 0.f;
        sw[idx] = val;
    }
    __syncthreads();

    // h tile with fused ELU
    for (int idx = tid; idx < 64 * 64; idx += 256) {
        int row = idx >> 6, c = idx & 63;
        size_t n = (size_t)(nb + row);
        float hv = g_A1[n * 64 + c] * sinv[row] + g_yroot[n * 64 + c] + sb[c];
        sh[row * 65 + c] = hv > 0.f ? hv : expm1f(hv);
    }
    __syncthreads();

    int og = tid & 15;   // 16 x 8 outs
    int ng = tid >> 4;   // 16 x 4 nodes
    float acc[4][8] = {};
    #pragma unroll 4
    for (int k = 0; k < 64; k++) {
        float w[8];
        *reinterpret_cast<float4*>(w)     = *reinterpret_cast<float4*>(sw + k * 128 + og * 8);
        *reinterpret_cast<float4*>(w + 4) = *reinterpret_cast<float4*>(sw + k * 128 + og * 8 + 4);
        #pragma unroll
        for (int i = 0; i < 4; i++) {
            float hr = sh[(ng * 4 + i) * 65 + k];
            #pragma unroll
            for (int j = 0; j < 8; j++) acc[i][j] += hr * w[j];
        }
    }

    int o0 = og * 8;
    #pragma unroll
    for (int i = 0; i < 4; i++) {
        int n = nb + ng * 4 + i;
        if (o0 < 80) {
            __half2 hv[4];
            #pragma unroll
            for (int q = 0; q < 4; q++)
                hv[q] = __floats2half2_rn(acc[i][2 * q], acc[i][2 * q + 1]);
            *reinterpret_cast<int4*>(g_z16 + (size_t)n * 80 + o0) =
                *reinterpret_cast<int4*>(hv);
        } else if (o0 < 120) {
            float* zp = g_zroot + (size_t)n * 40 + (o0 - 80);
            *reinterpret_cast<float4*>(zp)     = make_float4(acc[i][0], acc[i][1], acc[i][2], acc[i][3]);
            *reinterpret_cast<float4*>(zp + 4) = make_float4(acc[i][4], acc[i][5], acc[i][6], acc[i][7]);
        } // o0 == 120: padding, skip
    }
}

// ---------------------------------------------------------------------------
// scatter2: A2[dst] += z0[src] + v*zd[src].  5 lanes/edge, 8 halves each.
__global__ __launch_bounds__(256) void scatter2_kernel(
    const int* __restrict__ src,
    const int* __restrict__ dst,
    const float* __restrict__ ea)
{
    unsigned t = blockIdx.x * 256 + threadIdx.x;
    unsigned e = t / 5u;
    unsigned lane = t - e * 5u;
    int s = __ldg(src + e), d = __ldg(dst + e);
    float v = __ldg(ea + e);
    const int4* zr = reinterpret_cast<const int4*>(g_z16 + (size_t)s * 80);
    int4 p0 = __ldg(zr + lane);
    int4 pd = __ldg(zr + 5 + lane);
    float a0[8], ad[8];
    h8_to_f8(p0, a0);
    h8_to_f8(pd, ad);
    float m[8];
    #pragma unroll
    for (int q = 0; q < 8; q++) m[q] = fmaf(v, ad[q], a0[q]);
    float* Ap = g_A2 + (size_t)d * 40 + lane * 8;
    red_add_v4(Ap,     m[0], m[1], m[2], m[3]);
    red_add_v4(Ap + 4, m[4], m[5], m[6], m[7]);
}

// ---------------------------------------------------------------------------
// final: out = A2/deg + zroot + bias2
__global__ __launch_bounds__(256) void final_kernel(
    const float* __restrict__ bias2, float* __restrict__ out)
{
    unsigned t = blockIdx.x * 256 + threadIdx.x;   // NN*10 threads
    if (t >= NN * 10) return;
    unsigned n = t / 10u;
    unsigned l = t - n * 10u;
    float inv = 1.0f / fmaxf(g_deg[n], 1.0f);
    float4 a  = *reinterpret_cast<const float4*>(g_A2 + (size_t)n * 40 + l * 4);
    float4 zr = *reinterpret_cast<const float4*>(g_zroot + (size_t)n * 40 + l * 4);
    float4 b  = __ldg(reinterpret_cast<const float4*>(bias2) + l);
    float4 o;
    o.x = a.x * inv + zr.x + b.x;
    o.y = a.y * inv + zr.y + b.y;
    o.z = a.z * inv + zr.z + b.z;
    o.w = a.w * inv + zr.w + b.w;
    *reinterpret_cast<float4*>(out + (size_t)n * 40 + l * 4) = o;
}

// ---------------------------------------------------------------------------
extern "C" void kernel_launch(void* const* d_in, const int* in_sizes, int n_in,
                              void* d_out, int out_size)
{
    const float* x     = (const float*)d_in[0];
    const int*   eidx  = (const int*)  d_in[1];
    const float* ea    = (const float*)d_in[2];
    const float* W1    = (const float*)d_in[3];
    const float* root1 = (const float*)d_in[4];
    const float* bias1 = (const float*)d_in[5];
    const float* W2    = (const float*)d_in[6];
    const float* root2 = (const float*)d_in[7];
    const float* bias2 = (const float*)d_in[8];
    float* out = (float*)d_out;

    const int* src = eidx;
    const int* dst = eidx + NE;

    const int p1_smem = (128 * 96 + 64 * 36) * (int)sizeof(float);   // 58368 B
    const int p2_smem = (64 * 128 + 64 * 65) * (int)sizeof(float);   // 49408 B
    cudaFuncSetAttribute(proj1_kernel, cudaFuncAttributeMaxDynamicSharedMemorySize, p1_smem);
    cudaFuncSetAttribute(proj2_kernel, cudaFuncAttributeMaxDynamicSharedMemorySize, p2_smem);

    proj1_kernel<<<dim3(NPAD / 64, 2), 256, p1_smem>>>(x, W1, root1);
    scatter1_kernel<<<(NE * 8) / 256, 256>>>(src, dst, ea);
    proj2_kernel<<<NPAD / 64, 256, p2_smem>>>(W2, root2, bias1);
    scatter2_kernel<<<(NE * 5) / 256, 256>>>(src, dst, ea);
    final_kernel<<<(NN * 10 + 255) / 256, 256>>>(bias2, out);
}

// round 5
// speedup vs baseline: 1.0678x; 1.0678x over previous
#include <cuda_runtime.h>
#include <cuda_fp16.h>
#include <math.h>

#define NN    50000
#define NE    800000
#define F1    128
#define H     64
#define NCLS  40
#define NPAD  50176       // multiple of 64

__device__ float  g_A1[(size_t)NPAD * 64];     // layer-1 message accumulator
__device__ float  g_A2[(size_t)NPAD * 40];     // layer-2 message accumulator
__device__ float  g_deg[NPAD];
__device__ __half g_y16[(size_t)NPAD * 128];   // [ x@W0 | x@(W1-W0) ] fp16
__device__ float  g_yroot[(size_t)NPAD * 64];  // x@root1 fp32
__device__ __half g_z16[(size_t)NPAD * 80];    // [ h@W0' | h@(W1'-W0') ] fp16
__device__ float  g_zroot[(size_t)NPAD * 40];  // h@root2 fp32

// ---------------------------------------------------------------------------
__device__ __forceinline__ void red_add_v4(float* addr, float a, float b, float c, float d) {
    asm volatile("red.global.add.v4.f32 [%0], {%1,%2,%3,%4};"
                 :: "l"(addr), "f"(a), "f"(b), "f"(c), "f"(d) : "memory");
}

__device__ __forceinline__ void h8_to_f8(int4 p, float* f) {
    const __half2* h = reinterpret_cast<const __half2*>(&p);
    #pragma unroll
    for (int q = 0; q < 4; q++) {
        float2 t = __half22float2(h[q]);
        f[2 * q] = t.x; f[2 * q + 1] = t.y;
    }
}

// ---------------------------------------------------------------------------
// proj1: y[n] = x[n] @ [W0 | W1-W0 | root1]  (K=128, 192 outs split over grid.y)
// Also zeros A1 + deg for its node rows (grid.y==0 only).
__global__ __launch_bounds__(256) void proj1_kernel(
    const float* __restrict__ x,
    const float* __restrict__ W1,
    const float* __restrict__ root1)
{
    extern __shared__ float smem[];
    float* sw = smem;               // [128][96]
    float* sx = smem + 128 * 96;    // [64][36]
    int tid = threadIdx.x;
    int ob = blockIdx.y * 96;
    int nb = blockIdx.x * 64;

    if (blockIdx.y == 0) {          // zero A1 rows + deg for this node tile
        float4 z4 = make_float4(0.f, 0.f, 0.f, 0.f);
        float4* a = reinterpret_cast<float4*>(g_A1 + (size_t)nb * 64);
        for (int i = tid; i < 1024; i += 256) a[i] = z4;
        if (tid < 64) g_deg[nb + tid] = 0.f;
    }

    for (int idx = tid; idx < 128 * 96; idx += 256) {
        int k = idx / 96, oc = idx % 96, o = ob + oc;
        float val;
        if (o < 64)       val = W1[k * 64 + o];
        else if (o < 128) { int oo = o - 64; val = W1[128 * 64 + k * 64 + oo] - W1[k * 64 + oo]; }
        else              val = root1[k * 64 + (o - 128)];
        sw[idx] = val;
    }

    int og = tid & 15;   // 16 groups x 6 outs
    int ng = tid >> 4;   // 16 groups x 4 nodes
    float acc[4][6] = {};

    for (int kk = 0; kk < 128; kk += 32) {
        __syncthreads();
        #pragma unroll
        for (int r = 0; r < 2; r++) {
            int i = tid * 2 + r;
            int row = i >> 3, c = i & 7;
            int n = nb + row; if (n > NN - 1) n = NN - 1;
            float4 xv = __ldg(reinterpret_cast<const float4*>(x + (size_t)n * F1 + kk) + c);
            *reinterpret_cast<float4*>(sx + row * 36 + c * 4) = xv;
        }
        __syncthreads();
        #pragma unroll
        for (int k2 = 0; k2 < 32; k2++) {
            int kg = kk + k2;
            float w[6];
            *reinterpret_cast<float2*>(w + 0) = *reinterpret_cast<float2*>(sw + kg * 96 + og * 6);
            *reinterpret_cast<float2*>(w + 2) = *reinterpret_cast<float2*>(sw + kg * 96 + og * 6 + 2);
            *reinterpret_cast<float2*>(w + 4) = *reinterpret_cast<float2*>(sw + kg * 96 + og * 6 + 4);
            #pragma unroll
            for (int i = 0; i < 4; i++) {
                float xr = sx[(ng * 4 + i) * 36 + k2];
                #pragma unroll
                for (int j = 0; j < 6; j++) acc[i][j] += xr * w[j];
            }
        }
    }

    #pragma unroll
    for (int i = 0; i < 4; i++) {
        int n = nb + ng * 4 + i;
        #pragma unroll
        for (int j = 0; j < 6; j++) {
            int o = ob + og * 6 + j;
            if (o < 128) g_y16[(size_t)n * 128 + o] = __float2half_rn(acc[i][j]);
            else         g_yroot[(size_t)n * 64 + (o - 128)] = acc[i][j];
        }
    }
}

// ---------------------------------------------------------------------------
// scatter1: A1[dst] += y0[src] + v*yd[src] (fp16 gather, fp32 RED); deg[dst]++.
// 16 lanes/edge, each lane handles 4 halves (one int2) -> one red_add_v4.
// Indices loaded directly by every lane (L1 broadcast) -- no shfl, no branch.
__global__ __launch_bounds__(256) void scatter1_kernel(
    const int* __restrict__ src,
    const int* __restrict__ dst,
    const float* __restrict__ ea)
{
    int t = blockIdx.x * 256 + threadIdx.x;
    int e = t >> 4;
    int lane = t & 15;
    int s = __ldg(src + e);
    int d = __ldg(dst + e);
    float v = __ldg(ea + e);

    const int2* yr = reinterpret_cast<const int2*>(g_y16 + (size_t)s * 128);
    int2 p0 = __ldg(yr + lane);        // halves [lane*4, lane*4+4)
    int2 pd = __ldg(yr + 16 + lane);
    const __half2* h0 = reinterpret_cast<const __half2*>(&p0);
    const __half2* hd = reinterpret_cast<const __half2*>(&pd);
    float2 a0 = __half22float2(h0[0]);
    float2 a1 = __half22float2(h0[1]);
    float2 d0 = __half22float2(hd[0]);
    float2 d1 = __half22float2(hd[1]);
    red_add_v4(g_A1 + (size_t)d * 64 + lane * 4,
               fmaf(v, d0.x, a0.x), fmaf(v, d0.y, a0.y),
               fmaf(v, d1.x, a1.x), fmaf(v, d1.y, a1.y));
    if (lane == 0) atomicAdd(g_deg + d, 1.0f);
}

// ---------------------------------------------------------------------------
// proj2 (fused elu): h = elu(A1/deg + yroot + bias1) computed into SMEM,
// then z[n] = h[n] @ [W0' | W1'-W0' | root2 | 0]  (K=64, 128 outs, one block).
// Also zeros A2 for its node rows.
__global__ __launch_bounds__(256) void proj2_kernel(
    const float* __restrict__ W2,
    const float* __restrict__ root2,
    const float* __restrict__ bias1)
{
    extern __shared__ float smem[];
    float* sw = smem;               // [64][128]
    float* sh = smem + 64 * 128;    // [64][65]
    __shared__ float sinv[64];
    __shared__ float sb[64];
    int tid = threadIdx.x;
    int nb = blockIdx.x * 64;

    {   // zero A2 rows for this tile
        float4 z4 = make_float4(0.f, 0.f, 0.f, 0.f);
        float4* a = reinterpret_cast<float4*>(g_A2 + (size_t)nb * 40);
        for (int i = tid; i < 640; i += 256) a[i] = z4;
    }
    if (tid < 64) {
        sb[tid] = __ldg(bias1 + tid);
        sinv[tid] = 1.0f / fmaxf(g_deg[nb + tid], 1.0f);
    }

    for (int idx = tid; idx < 64 * 128; idx += 256) {
        int k = idx >> 7, o = idx & 127;
        float val;
        if (o < 40)       val = W2[k * 40 + o];
        else if (o < 80)  { int oo = o - 40; val = W2[64 * 40 + k * 40 + oo] - W2[k * 40 + oo]; }
        else if (o < 120) val = root2[k * 40 + (o - 80)];
        else              val = 0.f;
        sw[idx] = val;
    }
    __syncthreads();

    // h tile with fused ELU
    for (int idx = tid; idx < 64 * 64; idx += 256) {
        int row = idx >> 6, c = idx & 63;
        size_t n = (size_t)(nb + row);
        float hv = g_A1[n * 64 + c] * sinv[row] + g_yroot[n * 64 + c] + sb[c];
        sh[row * 65 + c] = hv > 0.f ? hv : expm1f(hv);
    }
    __syncthreads();

    int og = tid & 15;   // 16 x 8 outs
    int ng = tid >> 4;   // 16 x 4 nodes
    float acc[4][8] = {};
    #pragma unroll 4
    for (int k = 0; k < 64; k++) {
        float w[8];
        *reinterpret_cast<float4*>(w)     = *reinterpret_cast<float4*>(sw + k * 128 + og * 8);
        *reinterpret_cast<float4*>(w + 4) = *reinterpret_cast<float4*>(sw + k * 128 + og * 8 + 4);
        #pragma unroll
        for (int i = 0; i < 4; i++) {
            float hr = sh[(ng * 4 + i) * 65 + k];
            #pragma unroll
            for (int j = 0; j < 8; j++) acc[i][j] += hr * w[j];
        }
    }

    int o0 = og * 8;
    #pragma unroll
    for (int i = 0; i < 4; i++) {
        int n = nb + ng * 4 + i;
        if (o0 < 80) {
            __half2 hv[4];
            #pragma unroll
            for (int q = 0; q < 4; q++)
                hv[q] = __floats2half2_rn(acc[i][2 * q], acc[i][2 * q + 1]);
            *reinterpret_cast<int4*>(g_z16 + (size_t)n * 80 + o0) =
                *reinterpret_cast<int4*>(hv);
        } else if (o0 < 120) {
            float* zp = g_zroot + (size_t)n * 40 + (o0 - 80);
            *reinterpret_cast<float4*>(zp)     = make_float4(acc[i][0], acc[i][1], acc[i][2], acc[i][3]);
            *reinterpret_cast<float4*>(zp + 4) = make_float4(acc[i][4], acc[i][5], acc[i][6], acc[i][7]);
        } // o0 == 120: padding, skip
    }
}

// ---------------------------------------------------------------------------
// scatter2: A2[dst] += z0[src] + v*zd[src].  5 lanes/edge, 8 halves each.
__global__ __launch_bounds__(256) void scatter2_kernel(
    const int* __restrict__ src,
    const int* __restrict__ dst,
    const float* __restrict__ ea)
{
    unsigned t = blockIdx.x * 256 + threadIdx.x;
    unsigned e = t / 5u;
    unsigned lane = t - e * 5u;
    int s = __ldg(src + e), d = __ldg(dst + e);
    float v = __ldg(ea + e);
    const int4* zr = reinterpret_cast<const int4*>(g_z16 + (size_t)s * 80);
    int4 p0 = __ldg(zr + lane);
    int4 pd = __ldg(zr + 5 + lane);
    float a0[8], ad[8];
    h8_to_f8(p0, a0);
    h8_to_f8(pd, ad);
    float m[8];
    #pragma unroll
    for (int q = 0; q < 8; q++) m[q] = fmaf(v, ad[q], a0[q]);
    float* Ap = g_A2 + (size_t)d * 40 + lane * 8;
    red_add_v4(Ap,     m[0], m[1], m[2], m[3]);
    red_add_v4(Ap + 4, m[4], m[5], m[6], m[7]);
}

// ---------------------------------------------------------------------------
// final: out = A2/deg + zroot + bias2
__global__ __launch_bounds__(256) void final_kernel(
    const float* __restrict__ bias2, float* __restrict__ out)
{
    unsigned t = blockIdx.x * 256 + threadIdx.x;   // NN*10 threads
    if (t >= NN * 10) return;
    unsigned n = t / 10u;
    unsigned l = t - n * 10u;
    float inv = 1.0f / fmaxf(g_deg[n], 1.0f);
    float4 a  = *reinterpret_cast<const float4*>(g_A2 + (size_t)n * 40 + l * 4);
    float4 zr = *reinterpret_cast<const float4*>(g_zroot + (size_t)n * 40 + l * 4);
    float4 b  = __ldg(reinterpret_cast<const float4*>(bias2) + l);
    float4 o;
    o.x = a.x * inv + zr.x + b.x;
    o.y = a.y * inv + zr.y + b.y;
    o.z = a.z * inv + zr.z + b.z;
    o.w = a.w * inv + zr.w + b.w;
    *reinterpret_cast<float4*>(out + (size_t)n * 40 + l * 4) = o;
}

// ---------------------------------------------------------------------------
extern "C" void kernel_launch(void* const* d_in, const int* in_sizes, int n_in,
                              void* d_out, int out_size)
{
    const float* x     = (const float*)d_in[0];
    const int*   eidx  = (const int*)  d_in[1];
    const float* ea    = (const float*)d_in[2];
    const float* W1    = (const float*)d_in[3];
    const float* root1 = (const float*)d_in[4];
    const float* bias1 = (const float*)d_in[5];
    const float* W2    = (const float*)d_in[6];
    const float* root2 = (const float*)d_in[7];
    const float* bias2 = (const float*)d_in[8];
    float* out = (float*)d_out;

    const int* src = eidx;
    const int* dst = eidx + NE;

    const int p1_smem = (128 * 96 + 64 * 36) * (int)sizeof(float);   // 58368 B
    const int p2_smem = (64 * 128 + 64 * 65) * (int)sizeof(float);   // 49408 B
    cudaFuncSetAttribute(proj1_kernel, cudaFuncAttributeMaxDynamicSharedMemorySize, p1_smem);
    cudaFuncSetAttribute(proj2_kernel, cudaFuncAttributeMaxDynamicSharedMemorySize, p2_smem);

    proj1_kernel<<<dim3(NPAD / 64, 2), 256, p1_smem>>>(x, W1, root1);
    scatter1_kernel<<<(NE * 16) / 256, 256>>>(src, dst, ea);
    proj2_kernel<<<NPAD / 64, 256, p2_smem>>>(W2, root2, bias1);
    scatter2_kernel<<<(NE * 5) / 256, 256>>>(src, dst, ea);
    final_kernel<<<(NN * 10 + 255) / 256, 256>>>(bias2, out);
}

// round 6
// speedup vs baseline: 1.1322x; 1.0603x over previous
#include <cuda_runtime.h>
#include <cuda_fp16.h>
#include <math.h>

#define NN    50000
#define NE    800000
#define F1    128
#define H     64
#define NCLS  40
#define NPAD  50176       // multiple of 64

__device__ float  g_A1[(size_t)NPAD * 64];     // layer-1 message accumulator
__device__ float  g_A2[(size_t)NPAD * 40];     // layer-2 message accumulator
__device__ float  g_deg[NPAD];
__device__ __half g_y16[(size_t)NPAD * 128];   // [ x@W0 | x@(W1-W0) ] fp16
__device__ float  g_yroot[(size_t)NPAD * 64];  // x@root1 fp32
__device__ float  g_h[(size_t)NPAD * H];       // hidden activations fp32
__device__ __half g_z16[(size_t)NPAD * 80];    // [ h@W0' | h@(W1'-W0') ] fp16
__device__ float  g_zroot[(size_t)NPAD * 40];  // h@root2 fp32

// ---------------------------------------------------------------------------
__device__ __forceinline__ void red_add_v4(float* addr, float a, float b, float c, float d) {
    asm volatile("red.global.add.v4.f32 [%0], {%1,%2,%3,%4};"
                 :: "l"(addr), "f"(a), "f"(b), "f"(c), "f"(d) : "memory");
}

__device__ __forceinline__ void h8_to_f8(int4 p, float* f) {
    const __half2* h = reinterpret_cast<const __half2*>(&p);
    #pragma unroll
    for (int q = 0; q < 4; q++) {
        float2 t = __half22float2(h[q]);
        f[2 * q] = t.x; f[2 * q + 1] = t.y;
    }
}

// ---------------------------------------------------------------------------
// zero A1, A2, deg  (~21 MB)
#define ZFLOATS ((size_t)NPAD * 105)   // 64 + 40 + 1 per node
__global__ __launch_bounds__(256) void zero_kernel() {
    size_t i = (size_t)blockIdx.x * blockDim.x + threadIdx.x;
    size_t stride = (size_t)gridDim.x * blockDim.x;
    float4 z = make_float4(0.f, 0.f, 0.f, 0.f);
    float4* a1 = reinterpret_cast<float4*>(g_A1);
    float4* a2 = reinterpret_cast<float4*>(g_A2);
    for (size_t j = i; j < (size_t)NPAD * 16; j += stride) a1[j] = z;
    for (size_t j = i; j < (size_t)NPAD * 10; j += stride) a2[j] = z;
    for (size_t j = i; j < NPAD; j += stride) g_deg[j] = 0.f;
}

// ---------------------------------------------------------------------------
// proj1: y[n] = x[n] @ [W0 | W1-W0 | root1]  (K=128, 192 outs split over grid.y)
// R2-proven tiling; only stores differ (fp16 message part).
__global__ __launch_bounds__(256) void proj1_kernel(
    const float* __restrict__ x,
    const float* __restrict__ W1,
    const float* __restrict__ root1)
{
    extern __shared__ float smem[];
    float* sw = smem;               // [128][96]
    float* sx = smem + 128 * 96;    // [64][36]
    int tid = threadIdx.x;
    int ob = blockIdx.y * 96;
    int nb = blockIdx.x * 64;

    for (int idx = tid; idx < 128 * 96; idx += 256) {
        int k = idx / 96, oc = idx % 96, o = ob + oc;
        float val;
        if (o < 64)       val = W1[k * 64 + o];
        else if (o < 128) { int oo = o - 64; val = W1[128 * 64 + k * 64 + oo] - W1[k * 64 + oo]; }
        else              val = root1[k * 64 + (o - 128)];
        sw[idx] = val;
    }

    int og = tid & 15;   // 16 groups x 6 outs
    int ng = tid >> 4;   // 16 groups x 4 nodes
    float acc[4][6] = {};

    for (int kk = 0; kk < 128; kk += 32) {
        __syncthreads();
        #pragma unroll
        for (int r = 0; r < 2; r++) {
            int i = tid * 2 + r;
            int row = i >> 3, c = i & 7;
            int n = nb + row; if (n > NN - 1) n = NN - 1;
            float4 xv = __ldg(reinterpret_cast<const float4*>(x + (size_t)n * F1 + kk) + c);
            *reinterpret_cast<float4*>(sx + row * 36 + c * 4) = xv;
        }
        __syncthreads();
        #pragma unroll
        for (int k2 = 0; k2 < 32; k2++) {
            int kg = kk + k2;
            float w[6];
            *reinterpret_cast<float2*>(w + 0) = *reinterpret_cast<float2*>(sw + kg * 96 + og * 6);
            *reinterpret_cast<float2*>(w + 2) = *reinterpret_cast<float2*>(sw + kg * 96 + og * 6 + 2);
            *reinterpret_cast<float2*>(w + 4) = *reinterpret_cast<float2*>(sw + kg * 96 + og * 6 + 4);
            #pragma unroll
            for (int i = 0; i < 4; i++) {
                float xr = sx[(ng * 4 + i) * 36 + k2];
                #pragma unroll
                for (int j = 0; j < 6; j++) acc[i][j] += xr * w[j];
            }
        }
    }

    #pragma unroll
    for (int i = 0; i < 4; i++) {
        int n = nb + ng * 4 + i;
        #pragma unroll
        for (int j = 0; j < 6; j++) {
            int o = ob + og * 6 + j;
            if (o < 128) g_y16[(size_t)n * 128 + o] = __float2half_rn(acc[i][j]);
            else         g_yroot[(size_t)n * 64 + (o - 128)] = acc[i][j];
        }
    }
}

// ---------------------------------------------------------------------------
// scatter1: A1[dst] += y0[src] + v*yd[src] (fp16 gather, fp32 RED); deg[dst]++.
// 16 lanes/edge, one int2 (4 halves) per lane -> one red_add_v4.
__global__ __launch_bounds__(256) void scatter1_kernel(
    const int* __restrict__ src,
    const int* __restrict__ dst,
    const float* __restrict__ ea)
{
    int t = blockIdx.x * 256 + threadIdx.x;
    int e = t >> 4;
    int lane = t & 15;
    int s = __ldg(src + e);
    int d = __ldg(dst + e);
    float v = __ldg(ea + e);

    const int2* yr = reinterpret_cast<const int2*>(g_y16 + (size_t)s * 128);
    int2 p0 = __ldg(yr + lane);
    int2 pd = __ldg(yr + 16 + lane);
    const __half2* h0 = reinterpret_cast<const __half2*>(&p0);
    const __half2* hd = reinterpret_cast<const __half2*>(&pd);
    float2 a0 = __half22float2(h0[0]);
    float2 a1 = __half22float2(h0[1]);
    float2 d0 = __half22float2(hd[0]);
    float2 d1 = __half22float2(hd[1]);
    red_add_v4(g_A1 + (size_t)d * 64 + lane * 4,
               fmaf(v, d0.x, a0.x), fmaf(v, d0.y, a0.y),
               fmaf(v, d1.x, a1.x), fmaf(v, d1.y, a1.y));
    if (lane == 0) atomicAdd(g_deg + d, 1.0f);
}

// ---------------------------------------------------------------------------
// elu1: h = elu(A1/deg + yroot + bias1)     (float4 per thread)
__global__ __launch_bounds__(256) void elu1_kernel(const float* __restrict__ bias1)
{
    int t = blockIdx.x * 256 + threadIdx.x;       // NN*16 threads
    if (t >= NN * 16) return;
    int n = t >> 4, q = t & 15;
    float inv = 1.0f / fmaxf(g_deg[n], 1.0f);
    float4 a  = *reinterpret_cast<const float4*>(g_A1 + (size_t)n * 64 + q * 4);
    float4 yr = *reinterpret_cast<const float4*>(g_yroot + (size_t)n * 64 + q * 4);
    float4 b  = __ldg(reinterpret_cast<const float4*>(bias1) + q);
    float4 o;
    o.x = a.x * inv + yr.x + b.x;
    o.y = a.y * inv + yr.y + b.y;
    o.z = a.z * inv + yr.z + b.z;
    o.w = a.w * inv + yr.w + b.w;
    o.x = o.x > 0.f ? o.x : expm1f(o.x);
    o.y = o.y > 0.f ? o.y : expm1f(o.y);
    o.z = o.z > 0.f ? o.z : expm1f(o.z);
    o.w = o.w > 0.f ? o.w : expm1f(o.w);
    *reinterpret_cast<float4*>(g_h + (size_t)n * H + q * 4) = o;
}

// ---------------------------------------------------------------------------
// proj2: z[n] = h[n] @ [W0' | W1'-W0' | root2 | 0]  (K=64, 128 outs over grid.y)
// R2-proven tiling (64 nodes x 64 outs, thread 4x4); fp16 stores for o<80.
__global__ __launch_bounds__(256) void proj2_kernel(
    const float* __restrict__ W2,
    const float* __restrict__ root2)
{
    __shared__ float sw[64 * 64];
    __shared__ float sx[64 * 36];
    int tid = threadIdx.x;
    int ob = blockIdx.y * 64;
    int nb = blockIdx.x * 64;

    for (int idx = tid; idx < 64 * 64; idx += 256) {
        int k = idx >> 6, oc = idx & 63, o = ob + oc;
        float val;
        if (o < 40)       val = W2[k * 40 + o];
        else if (o < 80)  { int oo = o - 40; val = W2[64 * 40 + k * 40 + oo] - W2[k * 40 + oo]; }
        else if (o < 120) val = root2[k * 40 + (o - 80)];
        else              val = 0.f;
        sw[idx] = val;
    }

    int og = tid & 15;   // 16 x 4 outs
    int ng = tid >> 4;   // 16 x 4 nodes
    float acc[4][4] = {};

    for (int kk = 0; kk < 64; kk += 32) {
        __syncthreads();
        #pragma unroll
        for (int r = 0; r < 2; r++) {
            int i = tid * 2 + r;
            int row = i >> 3, c = i & 7;
            int n = nb + row; if (n > NN - 1) n = NN - 1;
            float4 hv = *reinterpret_cast<const float4*>(g_h + (size_t)n * H + kk + c * 4);
            *reinterpret_cast<float4*>(sx + row * 36 + c * 4) = hv;
        }
        __syncthreads();
        #pragma unroll
        for (int k2 = 0; k2 < 32; k2++) {
            int kg = kk + k2;
            float4 wv = *reinterpret_cast<float4*>(sw + kg * 64 + og * 4);
            #pragma unroll
            for (int i = 0; i < 4; i++) {
                float xr = sx[(ng * 4 + i) * 36 + k2];
                acc[i][0] += xr * wv.x;
                acc[i][1] += xr * wv.y;
                acc[i][2] += xr * wv.z;
                acc[i][3] += xr * wv.w;
            }
        }
    }

    int o0 = ob + og * 4;
    #pragma unroll
    for (int i = 0; i < 4; i++) {
        int n = nb + ng * 4 + i;
        if (o0 < 80) {         // message part -> fp16 (4 halves = int2, 8B aligned)
            __half2 hv[2];
            hv[0] = __floats2half2_rn(acc[i][0], acc[i][1]);
            hv[1] = __floats2half2_rn(acc[i][2], acc[i][3]);
            *reinterpret_cast<int2*>(g_z16 + (size_t)n * 80 + o0) =
                *reinterpret_cast<int2*>(hv);
        } else if (o0 < 120) { // root part -> fp32 float4
            *reinterpret_cast<float4*>(g_zroot + (size_t)n * 40 + (o0 - 80)) =
                make_float4(acc[i][0], acc[i][1], acc[i][2], acc[i][3]);
        } // o0 >= 120: padding
    }
}

// ---------------------------------------------------------------------------
// scatter2: A2[dst] += z0[src] + v*zd[src].  5 lanes/edge, 8 halves each.
// 2 edges per thread (e and e+NE/2) for doubled MLP.
__global__ __launch_bounds__(256) void scatter2_kernel(
    const int* __restrict__ src,
    const int* __restrict__ dst,
    const float* __restrict__ ea)
{
    unsigned t = blockIdx.x * 256 + threadIdx.x;
    if (t >= (NE / 2) * 5) return;
    unsigned e0 = t / 5u;
    unsigned lane = t - e0 * 5u;
    unsigned e1 = e0 + NE / 2;

    int s0 = __ldg(src + e0), d0i = __ldg(dst + e0);
    int s1 = __ldg(src + e1), d1i = __ldg(dst + e1);
    float v0 = __ldg(ea + e0);
    float v1 = __ldg(ea + e1);

    const int4* zr0 = reinterpret_cast<const int4*>(g_z16 + (size_t)s0 * 80);
    const int4* zr1 = reinterpret_cast<const int4*>(g_z16 + (size_t)s1 * 80);
    int4 p00 = __ldg(zr0 + lane);
    int4 p0d = __ldg(zr0 + 5 + lane);
    int4 p10 = __ldg(zr1 + lane);
    int4 p1d = __ldg(zr1 + 5 + lane);

    float a0[8], ad[8], b0[8], bd[8];
    h8_to_f8(p00, a0); h8_to_f8(p0d, ad);
    h8_to_f8(p10, b0); h8_to_f8(p1d, bd);

    float m0[8], m1[8];
    #pragma unroll
    for (int q = 0; q < 8; q++) {
        m0[q] = fmaf(v0, ad[q], a0[q]);
        m1[q] = fmaf(v1, bd[q], b0[q]);
    }
    float* A0 = g_A2 + (size_t)d0i * 40 + lane * 8;
    float* A1p = g_A2 + (size_t)d1i * 40 + lane * 8;
    red_add_v4(A0,      m0[0], m0[1], m0[2], m0[3]);
    red_add_v4(A0 + 4,  m0[4], m0[5], m0[6], m0[7]);
    red_add_v4(A1p,     m1[0], m1[1], m1[2], m1[3]);
    red_add_v4(A1p + 4, m1[4], m1[5], m1[6], m1[7]);
}

// ---------------------------------------------------------------------------
// final: out = A2/deg + zroot + bias2
__global__ __launch_bounds__(256) void final_kernel(
    const float* __restrict__ bias2, float* __restrict__ out)
{
    unsigned t = blockIdx.x * 256 + threadIdx.x;   // NN*10 threads
    if (t >= NN * 10) return;
    unsigned n = t / 10u;
    unsigned l = t - n * 10u;
    float inv = 1.0f / fmaxf(g_deg[n], 1.0f);
    float4 a  = *reinterpret_cast<const float4*>(g_A2 + (size_t)n * 40 + l * 4);
    float4 zr = *reinterpret_cast<const float4*>(g_zroot + (size_t)n * 40 + l * 4);
    float4 b  = __ldg(reinterpret_cast<const float4*>(bias2) + l);
    float4 o;
    o.x = a.x * inv + zr.x + b.x;
    o.y = a.y * inv + zr.y + b.y;
    o.z = a.z * inv + zr.z + b.z;
    o.w = a.w * inv + zr.w + b.w;
    *reinterpret_cast<float4*>(out + (size_t)n * 40 + l * 4) = o;
}

// ---------------------------------------------------------------------------
extern "C" void kernel_launch(void* const* d_in, const int* in_sizes, int n_in,
                              void* d_out, int out_size)
{
    const float* x     = (const float*)d_in[0];
    const int*   eidx  = (const int*)  d_in[1];
    const float* ea    = (const float*)d_in[2];
    const float* W1    = (const float*)d_in[3];
    const float* root1 = (const float*)d_in[4];
    const float* bias1 = (const float*)d_in[5];
    const float* W2    = (const float*)d_in[6];
    const float* root2 = (const float*)d_in[7];
    const float* bias2 = (const float*)d_in[8];
    float* out = (float*)d_out;

    const int* src = eidx;
    const int* dst = eidx + NE;

    const int p1_smem = (128 * 96 + 64 * 36) * (int)sizeof(float);   // 58368 B
    cudaFuncSetAttribute(proj1_kernel, cudaFuncAttributeMaxDynamicSharedMemorySize, p1_smem);

    zero_kernel<<<2048, 256>>>();
    proj1_kernel<<<dim3(NPAD / 64, 2), 256, p1_smem>>>(x, W1, root1);
    scatter1_kernel<<<(NE * 16) / 256, 256>>>(src, dst, ea);
    elu1_kernel<<<(NN * 16 + 255) / 256, 256>>>(bias1);
    proj2_kernel<<<dim3(NPAD / 64, 2), 256>>>(W2, root2);
    scatter2_kernel<<<((NE / 2) * 5 + 255) / 256, 256>>>(src, dst, ea);
    final_kernel<<<(NN * 10 + 255) / 256, 256>>>(bias2, out);
}

// round 7
// speedup vs baseline: 1.4153x; 1.2501x over previous
#include <cuda_runtime.h>
#include <cuda_fp16.h>
#include <math.h>
#include <stdint.h>

#define NN    50000
#define NE    800000
#define F1    128
#define H     64
#define NCLS  40
#define NPAD  50176       // multiple of 64

__device__ float  g_A1[(size_t)NPAD * 64];     // layer-1 message accumulator
__device__ float  g_A2[(size_t)NPAD * 40];     // layer-2 message accumulator
__device__ float  g_deg[NPAD];
__device__ __half g_y16[(size_t)NPAD * 128];   // [ x@W0 | x@(W1-W0) ] fp16
__device__ float  g_yroot[(size_t)NPAD * 64];  // x@root1 fp32
__device__ float  g_h[(size_t)NPAD * H];       // hidden activations fp32
__device__ __half g_z16[(size_t)NPAD * 80];    // [ h@W0' | h@(W1'-W0') ] fp16
__device__ float  g_zroot[(size_t)NPAD * 40];  // h@root2 fp32

// ---------------------------------------------------------------------------
__device__ __forceinline__ void red_add_v4(float* addr, float a, float b, float c, float d) {
    asm volatile("red.global.add.v4.f32 [%0], {%1,%2,%3,%4};"
                 :: "l"(addr), "f"(a), "f"(b), "f"(c), "f"(d) : "memory");
}

__device__ __forceinline__ void h8_to_f8(int4 p, float* f) {
    const __half2* h = reinterpret_cast<const __half2*>(&p);
    #pragma unroll
    for (int q = 0; q < 4; q++) {
        float2 t = __half22float2(h[q]);
        f[2 * q] = t.x; f[2 * q + 1] = t.y;
    }
}

__device__ __forceinline__ void ldsm_x4(uint32_t addr, uint32_t& r0, uint32_t& r1,
                                        uint32_t& r2, uint32_t& r3) {
    asm volatile("ldmatrix.sync.aligned.m8n8.x4.shared.b16 {%0,%1,%2,%3}, [%4];"
                 : "=r"(r0), "=r"(r1), "=r"(r2), "=r"(r3) : "r"(addr));
}

__device__ __forceinline__ void mma16816(float* c, const uint32_t* a, uint32_t b0, uint32_t b1) {
    asm volatile("mma.sync.aligned.m16n8k16.row.col.f32.f16.f16.f32 "
                 "{%0,%1,%2,%3}, {%4,%5,%6,%7}, {%8,%9}, {%0,%1,%2,%3};"
                 : "+f"(c[0]), "+f"(c[1]), "+f"(c[2]), "+f"(c[3])
                 : "r"(a[0]), "r"(a[1]), "r"(a[2]), "r"(a[3]), "r"(b0), "r"(b1));
}

// ---------------------------------------------------------------------------
// zero A1, A2, deg  (~21 MB)
__global__ __launch_bounds__(256) void zero_kernel() {
    size_t i = (size_t)blockIdx.x * blockDim.x + threadIdx.x;
    size_t stride = (size_t)gridDim.x * blockDim.x;
    float4 z = make_float4(0.f, 0.f, 0.f, 0.f);
    float4* a1 = reinterpret_cast<float4*>(g_A1);
    float4* a2 = reinterpret_cast<float4*>(g_A2);
    for (size_t j = i; j < (size_t)NPAD * 16; j += stride) a1[j] = z;
    for (size_t j = i; j < (size_t)NPAD * 10; j += stride) a2[j] = z;
    for (size_t j = i; j < NPAD; j += stride) g_deg[j] = 0.f;
}

// ---------------------------------------------------------------------------
// proj1 (HMMA): y[n, 0:192] = x[n] @ [W0 | W1-W0 | root1], fp16 in / fp32 acc.
// One block = 64 nodes x 192 outs. 256 thr = 8 warps: 4 along M x 2 along N(96).
// sA [64 rows][16 granules of 8 halves], sBt [192 rows(o)][16 granules] (k-major),
// both XOR-swizzled: granule g stored at g ^ (row & 7).
__global__ __launch_bounds__(256) void proj1_kernel(
    const float* __restrict__ x,
    const float* __restrict__ W1,
    const float* __restrict__ root1)
{
    extern __shared__ __half hsmem[];
    __half* sA  = hsmem;              // 64*128 halves = 16 KB
    __half* sBt = hsmem + 64 * 128;   // 192*128 halves = 48 KB
    const int tid = threadIdx.x;
    const int nb  = blockIdx.x * 64;

    // ---- fill sA: x rows (fp32 -> fp16), 1024 granules
    for (int idx = tid; idx < 64 * 16; idx += 256) {
        int row = idx >> 4, g = idx & 15;
        int n = nb + row; if (n > NN - 1) n = NN - 1;
        const float4* xp = reinterpret_cast<const float4*>(x + (size_t)n * F1 + g * 8);
        float4 f0 = __ldg(xp);
        float4 f1 = __ldg(xp + 1);
        __half2 hh[4];
        hh[0] = __floats2half2_rn(f0.x, f0.y);
        hh[1] = __floats2half2_rn(f0.z, f0.w);
        hh[2] = __floats2half2_rn(f1.x, f1.y);
        hh[3] = __floats2half2_rn(f1.z, f1.w);
        *reinterpret_cast<int4*>(sA + (row * 16 + (g ^ (row & 7))) * 8) =
            *reinterpret_cast<int4*>(hh);
    }

    // ---- fill sBt: sBt[o][k] = Wcat[k][o], 3072 granules
    for (int idx = tid; idx < 192 * 16; idx += 256) {
        int o = idx >> 4, g = idx & 15;
        __half hv[8];
        #pragma unroll
        for (int j = 0; j < 8; j++) {
            int k = g * 8 + j;
            float val;
            if (o < 64)       val = __ldg(W1 + k * 64 + o);
            else if (o < 128) { int oo = o - 64;
                                val = __ldg(W1 + 128 * 64 + k * 64 + oo) - __ldg(W1 + k * 64 + oo); }
            else              val = __ldg(root1 + k * 64 + (o - 128));
            hv[j] = __float2half_rn(val);
        }
        *reinterpret_cast<int4*>(sBt + (o * 16 + (g ^ (o & 7))) * 8) =
            *reinterpret_cast<int4*>(hv);
    }
    __syncthreads();

    const int wid = tid >> 5;
    const int l   = tid & 31;
    const int m_base = (wid & 3) * 16;     // 0,16,32,48
    const int n_base = (wid >> 2) * 96;    // 0 or 96

    uint32_t sA_u  = (uint32_t)__cvta_generic_to_shared(sA);
    uint32_t sBt_u = (uint32_t)__cvta_generic_to_shared(sBt);

    // per-lane ldmatrix row indices
    const int rowA = m_base + (l & 7) + ((l >> 3) & 1) * 8;       // x4 A: m0/m1 rows, m2/m3 = +k granule
    const int aGsel = (l >> 4) & 1;                               // matrices 2,3 -> k granule +1
    // B: matrices (n,g),(n,g+1),(n+8,g),(n+8,g+1)
    const int bRowOff = (l & 7) + ((l >> 4) & 1) * 8;
    const int bGsel = (l >> 3) & 1;

    float acc[12][4] = {};

    #pragma unroll
    for (int ks = 0; ks < 8; ks++) {
        int g2 = ks * 2;
        uint32_t a[4];
        {
            int gs = g2 + aGsel;
            uint32_t addr = sA_u + (uint32_t)((rowA * 16 + (gs ^ (rowA & 7))) * 16);
            ldsm_x4(addr, a[0], a[1], a[2], a[3]);
        }
        #pragma unroll
        for (int p = 0; p < 6; p++) {
            int nrow = n_base + p * 16 + bRowOff;
            int gs = g2 + bGsel;
            uint32_t addr = sBt_u + (uint32_t)((nrow * 16 + (gs ^ (nrow & 7))) * 16);
            uint32_t b0, b1, b2, b3;
            ldsm_x4(addr, b0, b1, b2, b3);
            mma16816(acc[2 * p],     a, b0, b1);
            mma16816(acc[2 * p + 1], a, b2, b3);
        }
    }

    // ---- store C
    const int r0 = nb + m_base + (l >> 2);
    const int r1 = r0 + 8;
    const int cofs = (l & 3) * 2;
    #pragma unroll
    for (int p = 0; p < 6; p++) {
        #pragma unroll
        for (int hh = 0; hh < 2; hh++) {
            int t2 = 2 * p + hh;
            int o = n_base + p * 16 + hh * 8 + cofs;
            if (o < 128) {
                *reinterpret_cast<__half2*>(g_y16 + (size_t)r0 * 128 + o) =
                    __floats2half2_rn(acc[t2][0], acc[t2][1]);
                *reinterpret_cast<__half2*>(g_y16 + (size_t)r1 * 128 + o) =
                    __floats2half2_rn(acc[t2][2], acc[t2][3]);
            } else {
                *reinterpret_cast<float2*>(g_yroot + (size_t)r0 * 64 + (o - 128)) =
                    make_float2(acc[t2][0], acc[t2][1]);
                *reinterpret_cast<float2*>(g_yroot + (size_t)r1 * 64 + (o - 128)) =
                    make_float2(acc[t2][2], acc[t2][3]);
            }
        }
    }
}

// ---------------------------------------------------------------------------
// scatter1: A1[dst] += y0[src] + v*yd[src]; deg[dst]++.  16 lanes/edge,
// 2 edges per thread (e and e+NE/2) for doubled MLP.
__global__ __launch_bounds__(256) void scatter1_kernel(
    const int* __restrict__ src,
    const int* __restrict__ dst,
    const float* __restrict__ ea)
{
    int t = blockIdx.x * 256 + threadIdx.x;     // (NE/2)*16 threads
    int e0 = t >> 4;
    int lane = t & 15;
    int e1 = e0 + NE / 2;

    int s0 = __ldg(src + e0), d0 = __ldg(dst + e0);
    int s1 = __ldg(src + e1), d1 = __ldg(dst + e1);
    float v0 = __ldg(ea + e0);
    float v1 = __ldg(ea + e1);

    const int2* yr0 = reinterpret_cast<const int2*>(g_y16 + (size_t)s0 * 128);
    const int2* yr1 = reinterpret_cast<const int2*>(g_y16 + (size_t)s1 * 128);
    int2 p00 = __ldg(yr0 + lane);
    int2 p0d = __ldg(yr0 + 16 + lane);
    int2 p10 = __ldg(yr1 + lane);
    int2 p1d = __ldg(yr1 + 16 + lane);

    const __half2* h00 = reinterpret_cast<const __half2*>(&p00);
    const __half2* h0d = reinterpret_cast<const __half2*>(&p0d);
    const __half2* h10 = reinterpret_cast<const __half2*>(&p10);
    const __half2* h1d = reinterpret_cast<const __half2*>(&p1d);

    float2 a0 = __half22float2(h00[0]), a1 = __half22float2(h00[1]);
    float2 da0 = __half22float2(h0d[0]), da1 = __half22float2(h0d[1]);
    float2 b0 = __half22float2(h10[0]), b1 = __half22float2(h10[1]);
    float2 db0 = __half22float2(h1d[0]), db1 = __half22float2(h1d[1]);

    red_add_v4(g_A1 + (size_t)d0 * 64 + lane * 4,
               fmaf(v0, da0.x, a0.x), fmaf(v0, da0.y, a0.y),
               fmaf(v0, da1.x, a1.x), fmaf(v0, da1.y, a1.y));
    red_add_v4(g_A1 + (size_t)d1 * 64 + lane * 4,
               fmaf(v1, db0.x, b0.x), fmaf(v1, db0.y, b0.y),
               fmaf(v1, db1.x, b1.x), fmaf(v1, db1.y, b1.y));
    if (lane == 0) {
        atomicAdd(g_deg + d0, 1.0f);
        atomicAdd(g_deg + d1, 1.0f);
    }
}

// ---------------------------------------------------------------------------
// elu1: h = elu(A1/deg + yroot + bias1)
__global__ __launch_bounds__(256) void elu1_kernel(const float* __restrict__ bias1)
{
    int t = blockIdx.x * 256 + threadIdx.x;       // NN*16 threads
    if (t >= NN * 16) return;
    int n = t >> 4, q = t & 15;
    float inv = 1.0f / fmaxf(g_deg[n], 1.0f);
    float4 a  = *reinterpret_cast<const float4*>(g_A1 + (size_t)n * 64 + q * 4);
    float4 yr = *reinterpret_cast<const float4*>(g_yroot + (size_t)n * 64 + q * 4);
    float4 b  = __ldg(reinterpret_cast<const float4*>(bias1) + q);
    float4 o;
    o.x = a.x * inv + yr.x + b.x;
    o.y = a.y * inv + yr.y + b.y;
    o.z = a.z * inv + yr.z + b.z;
    o.w = a.w * inv + yr.w + b.w;
    o.x = o.x > 0.f ? o.x : expm1f(o.x);
    o.y = o.y > 0.f ? o.y : expm1f(o.y);
    o.z = o.z > 0.f ? o.z : expm1f(o.z);
    o.w = o.w > 0.f ? o.w : expm1f(o.w);
    *reinterpret_cast<float4*>(g_h + (size_t)n * H + q * 4) = o;
}

// ---------------------------------------------------------------------------
// proj2: z[n] = h[n] @ [W0' | W1'-W0' | root2 | 0]  (K=64, 128 outs over grid.y)
__global__ __launch_bounds__(256) void proj2_kernel(
    const float* __restrict__ W2,
    const float* __restrict__ root2)
{
    __shared__ float sw[64 * 64];
    __shared__ float sx[64 * 36];
    int tid = threadIdx.x;
    int ob = blockIdx.y * 64;
    int nb = blockIdx.x * 64;

    for (int idx = tid; idx < 64 * 64; idx += 256) {
        int k = idx >> 6, oc = idx & 63, o = ob + oc;
        float val;
        if (o < 40)       val = W2[k * 40 + o];
        else if (o < 80)  { int oo = o - 40; val = W2[64 * 40 + k * 40 + oo] - W2[k * 40 + oo]; }
        else if (o < 120) val = root2[k * 40 + (o - 80)];
        else              val = 0.f;
        sw[idx] = val;
    }

    int og = tid & 15;   // 16 x 4 outs
    int ng = tid >> 4;   // 16 x 4 nodes
    float acc[4][4] = {};

    for (int kk = 0; kk < 64; kk += 32) {
        __syncthreads();
        #pragma unroll
        for (int r = 0; r < 2; r++) {
            int i = tid * 2 + r;
            int row = i >> 3, c = i & 7;
            int n = nb + row; if (n > NN - 1) n = NN - 1;
            float4 hv = *reinterpret_cast<const float4*>(g_h + (size_t)n * H + kk + c * 4);
            *reinterpret_cast<float4*>(sx + row * 36 + c * 4) = hv;
        }
        __syncthreads();
        #pragma unroll
        for (int k2 = 0; k2 < 32; k2++) {
            int kg = kk + k2;
            float4 wv = *reinterpret_cast<float4*>(sw + kg * 64 + og * 4);
            #pragma unroll
            for (int i = 0; i < 4; i++) {
                float xr = sx[(ng * 4 + i) * 36 + k2];
                acc[i][0] += xr * wv.x;
                acc[i][1] += xr * wv.y;
                acc[i][2] += xr * wv.z;
                acc[i][3] += xr * wv.w;
            }
        }
    }

    int o0 = ob + og * 4;
    #pragma unroll
    for (int i = 0; i < 4; i++) {
        int n = nb + ng * 4 + i;
        if (o0 < 80) {
            __half2 hv[2];
            hv[0] = __floats2half2_rn(acc[i][0], acc[i][1]);
            hv[1] = __floats2half2_rn(acc[i][2], acc[i][3]);
            *reinterpret_cast<int2*>(g_z16 + (size_t)n * 80 + o0) =
                *reinterpret_cast<int2*>(hv);
        } else if (o0 < 120) {
            *reinterpret_cast<float4*>(g_zroot + (size_t)n * 40 + (o0 - 80)) =
                make_float4(acc[i][0], acc[i][1], acc[i][2], acc[i][3]);
        }
    }
}

// ---------------------------------------------------------------------------
// scatter2: A2[dst] += z0[src] + v*zd[src].  5 lanes/edge, 2 edges/thread.
__global__ __launch_bounds__(256) void scatter2_kernel(
    const int* __restrict__ src,
    const int* __restrict__ dst,
    const float* __restrict__ ea)
{
    unsigned t = blockIdx.x * 256 + threadIdx.x;
    if (t >= (NE / 2) * 5) return;
    unsigned e0 = t / 5u;
    unsigned lane = t - e0 * 5u;
    unsigned e1 = e0 + NE / 2;

    int s0 = __ldg(src + e0), d0i = __ldg(dst + e0);
    int s1 = __ldg(src + e1), d1i = __ldg(dst + e1);
    float v0 = __ldg(ea + e0);
    float v1 = __ldg(ea + e1);

    const int4* zr0 = reinterpret_cast<const int4*>(g_z16 + (size_t)s0 * 80);
    const int4* zr1 = reinterpret_cast<const int4*>(g_z16 + (size_t)s1 * 80);
    int4 p00 = __ldg(zr0 + lane);
    int4 p0d = __ldg(zr0 + 5 + lane);
    int4 p10 = __ldg(zr1 + lane);
    int4 p1d = __ldg(zr1 + 5 + lane);

    float a0[8], ad[8], b0[8], bd[8];
    h8_to_f8(p00, a0); h8_to_f8(p0d, ad);
    h8_to_f8(p10, b0); h8_to_f8(p1d, bd);

    float m0[8], m1[8];
    #pragma unroll
    for (int q = 0; q < 8; q++) {
        m0[q] = fmaf(v0, ad[q], a0[q]);
        m1[q] = fmaf(v1, bd[q], b0[q]);
    }
    float* A0 = g_A2 + (size_t)d0i * 40 + lane * 8;
    float* A1p = g_A2 + (size_t)d1i * 40 + lane * 8;
    red_add_v4(A0,      m0[0], m0[1], m0[2], m0[3]);
    red_add_v4(A0 + 4,  m0[4], m0[5], m0[6], m0[7]);
    red_add_v4(A1p,     m1[0], m1[1], m1[2], m1[3]);
    red_add_v4(A1p + 4, m1[4], m1[5], m1[6], m1[7]);
}

// ---------------------------------------------------------------------------
// final: out = A2/deg + zroot + bias2
__global__ __launch_bounds__(256) void final_kernel(
    const float* __restrict__ bias2, float* __restrict__ out)
{
    unsigned t = blockIdx.x * 256 + threadIdx.x;   // NN*10 threads
    if (t >= NN * 10) return;
    unsigned n = t / 10u;
    unsigned l = t - n * 10u;
    float inv = 1.0f / fmaxf(g_deg[n], 1.0f);
    float4 a  = *reinterpret_cast<const float4*>(g_A2 + (size_t)n * 40 + l * 4);
    float4 zr = *reinterpret_cast<const float4*>(g_zroot + (size_t)n * 40 + l * 4);
    float4 b  = __ldg(reinterpret_cast<const float4*>(bias2) + l);
    float4 o;
    o.x = a.x * inv + zr.x + b.x;
    o.y = a.y * inv + zr.y + b.y;
    o.z = a.z * inv + zr.z + b.z;
    o.w = a.w * inv + zr.w + b.w;
    *reinterpret_cast<float4*>(out + (size_t)n * 40 + l * 4) = o;
}

// ---------------------------------------------------------------------------
extern "C" void kernel_launch(void* const* d_in, const int* in_sizes, int n_in,
                              void* d_out, int out_size)
{
    const float* x     = (const float*)d_in[0];
    const int*   eidx  = (const int*)  d_in[1];
    const float* ea    = (const float*)d_in[2];
    const float* W1    = (const float*)d_in[3];
    const float* root1 = (const float*)d_in[4];
    const float* bias1 = (const float*)d_in[5];
    const float* W2    = (const float*)d_in[6];
    const float* root2 = (const float*)d_in[7];
    const float* bias2 = (const float*)d_in[8];
    float* out = (float*)d_out;

    const int* src = eidx;
    const int* dst = eidx + NE;

    const int p1_smem = 256 * 128 * (int)sizeof(__half);   // 65536 B (sA 16K + sBt 48K)
    cudaFuncSetAttribute(proj1_kernel, cudaFuncAttributeMaxDynamicSharedMemorySize, p1_smem);

    zero_kernel<<<2048, 256>>>();
    proj1_kernel<<<NPAD / 64, 256, p1_smem>>>(x, W1, root1);
    scatter1_kernel<<<((NE / 2) * 16) / 256, 256>>>(src, dst, ea);
    elu1_kernel<<<(NN * 16 + 255) / 256, 256>>>(bias1);
    proj2_kernel<<<dim3(NPAD / 64, 2), 256>>>(W2, root2);
    scatter2_kernel<<<((NE / 2) * 5 + 255) / 256, 256>>>(src, dst, ea);
    final_kernel<<<(NN * 10 + 255) / 256, 256>>>(bias2, out);
}

// round 8
// speedup vs baseline: 1.5852x; 1.1201x over previous
#include <cuda_runtime.h>
#include <cuda_fp16.h>
#include <math.h>
#include <stdint.h>

#define NN    50000
#define NE    800000
#define F1    128
#define H     64
#define NCLS  40
#define NPAD  50176       // multiple of 64

__device__ float  g_A1[(size_t)NPAD * 64];     // layer-1 message accumulator
__device__ float  g_A2[(size_t)NPAD * 40];     // layer-2 message accumulator
__device__ float  g_deg[NPAD];
__device__ __half g_y16[(size_t)NPAD * 128];   // [ x@W0 | x@(W1-W0) ] fp16
__device__ float  g_yroot[(size_t)NPAD * 64];  // x@root1 fp32
__device__ __half g_z16[(size_t)NPAD * 80];    // [ h@W0' | h@(W1'-W0') ] fp16
__device__ float  g_zroot[(size_t)NPAD * 40];  // h@root2 fp32

// ---------------------------------------------------------------------------
__device__ __forceinline__ void red_add_v4(float* addr, float a, float b, float c, float d) {
    asm volatile("red.global.add.v4.f32 [%0], {%1,%2,%3,%4};"
                 :: "l"(addr), "f"(a), "f"(b), "f"(c), "f"(d) : "memory");
}

__device__ __forceinline__ void h8_to_f8(int4 p, float* f) {
    const __half2* h = reinterpret_cast<const __half2*>(&p);
    #pragma unroll
    for (int q = 0; q < 4; q++) {
        float2 t = __half22float2(h[q]);
        f[2 * q] = t.x; f[2 * q + 1] = t.y;
    }
}

__device__ __forceinline__ void ldsm_x4(uint32_t addr, uint32_t& r0, uint32_t& r1,
                                        uint32_t& r2, uint32_t& r3) {
    asm volatile("ldmatrix.sync.aligned.m8n8.x4.shared.b16 {%0,%1,%2,%3}, [%4];"
                 : "=r"(r0), "=r"(r1), "=r"(r2), "=r"(r3) : "r"(addr));
}

__device__ __forceinline__ void mma16816(float* c, const uint32_t* a, uint32_t b0, uint32_t b1) {
    asm volatile("mma.sync.aligned.m16n8k16.row.col.f32.f16.f16.f32 "
                 "{%0,%1,%2,%3}, {%4,%5,%6,%7}, {%8,%9}, {%0,%1,%2,%3};"
                 : "+f"(c[0]), "+f"(c[1]), "+f"(c[2]), "+f"(c[3])
                 : "r"(a[0]), "r"(a[1]), "r"(a[2]), "r"(a[3]), "r"(b0), "r"(b1));
}

// ---------------------------------------------------------------------------
// zero A1, A2, deg  (~21 MB)
__global__ __launch_bounds__(256) void zero_kernel() {
    size_t i = (size_t)blockIdx.x * blockDim.x + threadIdx.x;
    size_t stride = (size_t)gridDim.x * blockDim.x;
    float4 z = make_float4(0.f, 0.f, 0.f, 0.f);
    float4* a1 = reinterpret_cast<float4*>(g_A1);
    float4* a2 = reinterpret_cast<float4*>(g_A2);
    for (size_t j = i; j < (size_t)NPAD * 16; j += stride) a1[j] = z;
    for (size_t j = i; j < (size_t)NPAD * 10; j += stride) a2[j] = z;
    for (size_t j = i; j < NPAD; j += stride) g_deg[j] = 0.f;
}

// ---------------------------------------------------------------------------
// proj1 (HMMA): y[n, 0:192] = x[n] @ [W0 | W1-W0 | root1], fp16 in / fp32 acc.
// One block = 64 nodes x 192 outs. 8 warps: 4 along M x 2 along N(96).
__global__ __launch_bounds__(256) void proj1_kernel(
    const float* __restrict__ x,
    const float* __restrict__ W1,
    const float* __restrict__ root1)
{
    extern __shared__ __half hsmem[];
    __half* sA  = hsmem;              // 64*128 halves = 16 KB
    __half* sBt = hsmem + 64 * 128;   // 192*128 halves = 48 KB
    const int tid = threadIdx.x;
    const int nb  = blockIdx.x * 64;

    for (int idx = tid; idx < 64 * 16; idx += 256) {
        int row = idx >> 4, g = idx & 15;
        int n = nb + row; if (n > NN - 1) n = NN - 1;
        const float4* xp = reinterpret_cast<const float4*>(x + (size_t)n * F1 + g * 8);
        float4 f0 = __ldg(xp);
        float4 f1 = __ldg(xp + 1);
        __half2 hh[4];
        hh[0] = __floats2half2_rn(f0.x, f0.y);
        hh[1] = __floats2half2_rn(f0.z, f0.w);
        hh[2] = __floats2half2_rn(f1.x, f1.y);
        hh[3] = __floats2half2_rn(f1.z, f1.w);
        *reinterpret_cast<int4*>(sA + (row * 16 + (g ^ (row & 7))) * 8) =
            *reinterpret_cast<int4*>(hh);
    }

    for (int idx = tid; idx < 192 * 16; idx += 256) {
        int o = idx >> 4, g = idx & 15;
        __half hv[8];
        #pragma unroll
        for (int j = 0; j < 8; j++) {
            int k = g * 8 + j;
            float val;
            if (o < 64)       val = __ldg(W1 + k * 64 + o);
            else if (o < 128) { int oo = o - 64;
                                val = __ldg(W1 + 128 * 64 + k * 64 + oo) - __ldg(W1 + k * 64 + oo); }
            else              val = __ldg(root1 + k * 64 + (o - 128));
            hv[j] = __float2half_rn(val);
        }
        *reinterpret_cast<int4*>(sBt + (o * 16 + (g ^ (o & 7))) * 8) =
            *reinterpret_cast<int4*>(hv);
    }
    __syncthreads();

    const int wid = tid >> 5;
    const int l   = tid & 31;
    const int m_base = (wid & 3) * 16;
    const int n_base = (wid >> 2) * 96;

    uint32_t sA_u  = (uint32_t)__cvta_generic_to_shared(sA);
    uint32_t sBt_u = (uint32_t)__cvta_generic_to_shared(sBt);

    const int rowA = m_base + (l & 7) + ((l >> 3) & 1) * 8;
    const int aGsel = (l >> 4) & 1;
    const int bRowOff = (l & 7) + ((l >> 4) & 1) * 8;
    const int bGsel = (l >> 3) & 1;

    float acc[12][4] = {};

    #pragma unroll
    for (int ks = 0; ks < 8; ks++) {
        int g2 = ks * 2;
        uint32_t a[4];
        {
            int gs = g2 + aGsel;
            uint32_t addr = sA_u + (uint32_t)((rowA * 16 + (gs ^ (rowA & 7))) * 16);
            ldsm_x4(addr, a[0], a[1], a[2], a[3]);
        }
        #pragma unroll
        for (int p = 0; p < 6; p++) {
            int nrow = n_base + p * 16 + bRowOff;
            int gs = g2 + bGsel;
            uint32_t addr = sBt_u + (uint32_t)((nrow * 16 + (gs ^ (nrow & 7))) * 16);
            uint32_t b0, b1, b2, b3;
            ldsm_x4(addr, b0, b1, b2, b3);
            mma16816(acc[2 * p],     a, b0, b1);
            mma16816(acc[2 * p + 1], a, b2, b3);
        }
    }

    const int r0 = nb + m_base + (l >> 2);
    const int r1 = r0 + 8;
    const int cofs = (l & 3) * 2;
    #pragma unroll
    for (int p = 0; p < 6; p++) {
        #pragma unroll
        for (int hh = 0; hh < 2; hh++) {
            int t2 = 2 * p + hh;
            int o = n_base + p * 16 + hh * 8 + cofs;
            if (o < 128) {
                *reinterpret_cast<__half2*>(g_y16 + (size_t)r0 * 128 + o) =
                    __floats2half2_rn(acc[t2][0], acc[t2][1]);
                *reinterpret_cast<__half2*>(g_y16 + (size_t)r1 * 128 + o) =
                    __floats2half2_rn(acc[t2][2], acc[t2][3]);
            } else {
                *reinterpret_cast<float2*>(g_yroot + (size_t)r0 * 64 + (o - 128)) =
                    make_float2(acc[t2][0], acc[t2][1]);
                *reinterpret_cast<float2*>(g_yroot + (size_t)r1 * 64 + (o - 128)) =
                    make_float2(acc[t2][2], acc[t2][3]);
            }
        }
    }
}

// ---------------------------------------------------------------------------
// scatter1: A1[dst] += y0[src] + v*yd[src]; deg[dst]++.  16 lanes/edge,
// 4 edges per thread for quadrupled MLP.
__global__ __launch_bounds__(256) void scatter1_kernel(
    const int* __restrict__ src,
    const int* __restrict__ dst,
    const float* __restrict__ ea)
{
    int t = blockIdx.x * 256 + threadIdx.x;     // (NE/4)*16 threads
    int e0 = t >> 4;
    int lane = t & 15;

    #pragma unroll
    for (int u = 0; u < 4; u++) {
        int e = e0 + u * (NE / 4);
        int s = __ldg(src + e);
        int d = __ldg(dst + e);
        float v = __ldg(ea + e);
        const int2* yr = reinterpret_cast<const int2*>(g_y16 + (size_t)s * 128);
        int2 p0 = __ldg(yr + lane);
        int2 pd = __ldg(yr + 16 + lane);
        const __half2* h0 = reinterpret_cast<const __half2*>(&p0);
        const __half2* hd = reinterpret_cast<const __half2*>(&pd);
        float2 a0 = __half22float2(h0[0]), a1 = __half22float2(h0[1]);
        float2 d0 = __half22float2(hd[0]), d1 = __half22float2(hd[1]);
        red_add_v4(g_A1 + (size_t)d * 64 + lane * 4,
                   fmaf(v, d0.x, a0.x), fmaf(v, d0.y, a0.y),
                   fmaf(v, d1.x, a1.x), fmaf(v, d1.y, a1.y));
        if (lane == 0) atomicAdd(g_deg + d, 1.0f);
    }
}

// ---------------------------------------------------------------------------
// proj2 (HMMA, fused ELU): h = elu(A1/deg + yroot + bias1) -> fp16 SMEM,
// then z[n, 0:128] = h[n] @ [W0' | W1'-W0' | root2 | 0]  (m64 n128 k64).
__global__ __launch_bounds__(256) void proj2_kernel(
    const float* __restrict__ W2,
    const float* __restrict__ root2,
    const float* __restrict__ bias1)
{
    __shared__ __half sH[64 * 64];     // 8 KB
    __shared__ __half sBt[128 * 64];   // 16 KB
    const int tid = threadIdx.x;
    const int nb = blockIdx.x * 64;

    // ---- weights: sBt[o][k], swizzled granules of 8 halves
    for (int idx = tid; idx < 128 * 8; idx += 256) {
        int o = idx >> 3, g = idx & 7;
        __half hv[8];
        #pragma unroll
        for (int j = 0; j < 8; j++) {
            int k = g * 8 + j;
            float val;
            if (o < 40)       val = __ldg(W2 + k * 40 + o);
            else if (o < 80)  { int oo = o - 40;
                                val = __ldg(W2 + 64 * 40 + k * 40 + oo) - __ldg(W2 + k * 40 + oo); }
            else if (o < 120) val = __ldg(root2 + k * 40 + (o - 80));
            else              val = 0.f;
            hv[j] = __float2half_rn(val);
        }
        *reinterpret_cast<int4*>(sBt + (o * 8 + (g ^ (o & 7))) * 8) =
            *reinterpret_cast<int4*>(hv);
    }

    // ---- h tile with fused ELU: row = tid>>2, two granules per thread
    {
        int row = tid >> 2, gp = tid & 3;
        int n = nb + row;
        float inv = 1.0f / fmaxf(g_deg[n], 1.0f);
        #pragma unroll
        for (int gg = 0; gg < 2; gg++) {
            int g = gp * 2 + gg;
            const float4* ap = reinterpret_cast<const float4*>(g_A1 + (size_t)n * 64 + g * 8);
            const float4* yp = reinterpret_cast<const float4*>(g_yroot + (size_t)n * 64 + g * 8);
            const float4* bp = reinterpret_cast<const float4*>(bias1) + g * 2;
            float4 a0 = ap[0], a1 = ap[1];
            float4 y0 = yp[0], y1 = yp[1];
            float4 b0 = __ldg(bp), b1 = __ldg(bp + 1);
            float hv[8];
            hv[0] = a0.x * inv + y0.x + b0.x;
            hv[1] = a0.y * inv + y0.y + b0.y;
            hv[2] = a0.z * inv + y0.z + b0.z;
            hv[3] = a0.w * inv + y0.w + b0.w;
            hv[4] = a1.x * inv + y1.x + b1.x;
            hv[5] = a1.y * inv + y1.y + b1.y;
            hv[6] = a1.z * inv + y1.z + b1.z;
            hv[7] = a1.w * inv + y1.w + b1.w;
            __half2 hp[4];
            #pragma unroll
            for (int q = 0; q < 4; q++) {
                float u0 = hv[2 * q],     e0v = u0 > 0.f ? u0 : expm1f(u0);
                float u1 = hv[2 * q + 1], e1v = u1 > 0.f ? u1 : expm1f(u1);
                hp[q] = __floats2half2_rn(e0v, e1v);
            }
            *reinterpret_cast<int4*>(sH + (row * 8 + (g ^ (row & 7))) * 8) =
                *reinterpret_cast<int4*>(hp);
        }
    }
    __syncthreads();

    const int wid = tid >> 5;
    const int l   = tid & 31;
    const int m_base = (wid & 3) * 16;     // 0..48
    const int n_base = (wid >> 2) * 64;    // 0 or 64

    uint32_t sH_u  = (uint32_t)__cvta_generic_to_shared(sH);
    uint32_t sBt_u = (uint32_t)__cvta_generic_to_shared(sBt);

    const int rowA = m_base + (l & 7) + ((l >> 3) & 1) * 8;
    const int aGsel = (l >> 4) & 1;
    const int bRowOff = (l & 7) + ((l >> 4) & 1) * 8;
    const int bGsel = (l >> 3) & 1;

    float acc[8][4] = {};

    #pragma unroll
    for (int ks = 0; ks < 4; ks++) {
        int g2 = ks * 2;
        uint32_t a[4];
        {
            int gs = g2 + aGsel;
            uint32_t addr = sH_u + (uint32_t)((rowA * 8 + (gs ^ (rowA & 7))) * 16);
            ldsm_x4(addr, a[0], a[1], a[2], a[3]);
        }
        #pragma unroll
        for (int p = 0; p < 4; p++) {
            int nrow = n_base + p * 16 + bRowOff;
            int gs = g2 + bGsel;
            uint32_t addr = sBt_u + (uint32_t)((nrow * 8 + (gs ^ (nrow & 7))) * 16);
            uint32_t b0, b1, b2, b3;
            ldsm_x4(addr, b0, b1, b2, b3);
            mma16816(acc[2 * p],     a, b0, b1);
            mma16816(acc[2 * p + 1], a, b2, b3);
        }
    }

    const int r0 = nb + m_base + (l >> 2);
    const int r1 = r0 + 8;
    const int cofs = (l & 3) * 2;
    #pragma unroll
    for (int p = 0; p < 4; p++) {
        #pragma unroll
        for (int hh = 0; hh < 2; hh++) {
            int t2 = 2 * p + hh;
            int o = n_base + p * 16 + hh * 8 + cofs;
            if (o < 80) {
                *reinterpret_cast<__half2*>(g_z16 + (size_t)r0 * 80 + o) =
                    __floats2half2_rn(acc[t2][0], acc[t2][1]);
                *reinterpret_cast<__half2*>(g_z16 + (size_t)r1 * 80 + o) =
                    __floats2half2_rn(acc[t2][2], acc[t2][3]);
            } else if (o < 120) {
                *reinterpret_cast<float2*>(g_zroot + (size_t)r0 * 40 + (o - 80)) =
                    make_float2(acc[t2][0], acc[t2][1]);
                *reinterpret_cast<float2*>(g_zroot + (size_t)r1 * 40 + (o - 80)) =
                    make_float2(acc[t2][2], acc[t2][3]);
            }
        }
    }
}

// ---------------------------------------------------------------------------
// scatter2: A2[dst] += z0[src] + v*zd[src].  5 lanes/edge, 4 edges/thread.
__global__ __launch_bounds__(256) void scatter2_kernel(
    const int* __restrict__ src,
    const int* __restrict__ dst,
    const float* __restrict__ ea)
{
    unsigned t = blockIdx.x * 256 + threadIdx.x;
    if (t >= (NE / 4) * 5) return;
    unsigned e0 = t / 5u;
    unsigned lane = t - e0 * 5u;

    #pragma unroll
    for (int u = 0; u < 4; u++) {
        unsigned e = e0 + u * (NE / 4);
        int s = __ldg(src + e), d = __ldg(dst + e);
        float v = __ldg(ea + e);
        const int4* zr = reinterpret_cast<const int4*>(g_z16 + (size_t)s * 80);
        int4 p0 = __ldg(zr + lane);
        int4 pd = __ldg(zr + 5 + lane);
        float a0[8], ad[8];
        h8_to_f8(p0, a0); h8_to_f8(pd, ad);
        float m[8];
        #pragma unroll
        for (int q = 0; q < 8; q++) m[q] = fmaf(v, ad[q], a0[q]);
        float* Ap = g_A2 + (size_t)d * 40 + lane * 8;
        red_add_v4(Ap,     m[0], m[1], m[2], m[3]);
        red_add_v4(Ap + 4, m[4], m[5], m[6], m[7]);
    }
}

// ---------------------------------------------------------------------------
// final: out = A2/deg + zroot + bias2
__global__ __launch_bounds__(256) void final_kernel(
    const float* __restrict__ bias2, float* __restrict__ out)
{
    unsigned t = blockIdx.x * 256 + threadIdx.x;   // NN*10 threads
    if (t >= NN * 10) return;
    unsigned n = t / 10u;
    unsigned l = t - n * 10u;
    float inv = 1.0f / fmaxf(g_deg[n], 1.0f);
    float4 a  = *reinterpret_cast<const float4*>(g_A2 + (size_t)n * 40 + l * 4);
    float4 zr = *reinterpret_cast<const float4*>(g_zroot + (size_t)n * 40 + l * 4);
    float4 b  = __ldg(reinterpret_cast<const float4*>(bias2) + l);
    float4 o;
    o.x = a.x * inv + zr.x + b.x;
    o.y = a.y * inv + zr.y + b.y;
    o.z = a.z * inv + zr.z + b.z;
    o.w = a.w * inv + zr.w + b.w;
    *reinterpret_cast<float4*>(out + (size_t)n * 40 + l * 4) = o;
}

// ---------------------------------------------------------------------------
extern "C" void kernel_launch(void* const* d_in, const int* in_sizes, int n_in,
                              void* d_out, int out_size)
{
    const float* x     = (const float*)d_in[0];
    const int*   eidx  = (const int*)  d_in[1];
    const float* ea    = (const float*)d_in[2];
    const float* W1    = (const float*)d_in[3];
    const float* root1 = (const float*)d_in[4];
    const float* bias1 = (const float*)d_in[5];
    const float* W2    = (const float*)d_in[6];
    const float* root2 = (const float*)d_in[7];
    const float* bias2 = (const float*)d_in[8];
    float* out = (float*)d_out;

    const int* src = eidx;
    const int* dst = eidx + NE;

    const int p1_smem = 256 * 128 * (int)sizeof(__half);   // 65536 B
    cudaFuncSetAttribute(proj1_kernel, cudaFuncAttributeMaxDynamicSharedMemorySize, p1_smem);

    zero_kernel<<<2048, 256>>>();
    proj1_kernel<<<NPAD / 64, 256, p1_smem>>>(x, W1, root1);
    scatter1_kernel<<<((NE / 4) * 16) / 256, 256>>>(src, dst, ea);
    proj2_kernel<<<NPAD / 64, 256>>>(W2, root2, bias1);
    scatter2_kernel<<<((NE / 4) * 5 + 255) / 256, 256>>>(src, dst, ea);
    final_kernel<<<(NN * 10 + 255) / 256, 256>>>(bias2, out);
}

// round 9
// speedup vs baseline: 2.2232x; 1.4025x over previous
#include <cuda_runtime.h>
#include <cuda_fp16.h>
#include <math.h>
#include <stdint.h>

#define NN    50000
#define NE    800000
#define F1    128
#define H     64
#define NCLS  40
#define NPAD  50176       // multiple of 64

__device__ float  g_A1[(size_t)NPAD * 64];     // layer-1 message accumulator
__device__ float  g_A2[(size_t)NPAD * 40];     // layer-2 message accumulator
__device__ float  g_deg[NPAD];
__device__ __half g_y16[(size_t)NPAD * 128];   // [ x@W0 | x@(W1-W0) ] fp16
__device__ float  g_yroot[(size_t)NPAD * 64];  // x@root1 fp32
__device__ __half g_z16[(size_t)NPAD * 80];    // [ h@W0' | h@(W1'-W0') ] fp16
__device__ float  g_zroot[(size_t)NPAD * 40];  // h@root2 fp32
__device__ __half g_w1[192 * 128];             // proj1 weights, fp16, swizzled smem image
__device__ __half g_w2[128 * 64];              // proj2 weights, fp16, swizzled smem image

// ---------------------------------------------------------------------------
__device__ __forceinline__ void red_add_v4(float* addr, float a, float b, float c, float d) {
    asm volatile("red.global.add.v4.f32 [%0], {%1,%2,%3,%4};"
                 :: "l"(addr), "f"(a), "f"(b), "f"(c), "f"(d) : "memory");
}

__device__ __forceinline__ void h8_to_f8(int4 p, float* f) {
    const __half2* h = reinterpret_cast<const __half2*>(&p);
    #pragma unroll
    for (int q = 0; q < 4; q++) {
        float2 t = __half22float2(h[q]);
        f[2 * q] = t.x; f[2 * q + 1] = t.y;
    }
}

__device__ __forceinline__ void ldsm_x4(uint32_t addr, uint32_t& r0, uint32_t& r1,
                                        uint32_t& r2, uint32_t& r3) {
    asm volatile("ldmatrix.sync.aligned.m8n8.x4.shared.b16 {%0,%1,%2,%3}, [%4];"
                 : "=r"(r0), "=r"(r1), "=r"(r2), "=r"(r3) : "r"(addr));
}

__device__ __forceinline__ void mma16816(float* c, const uint32_t* a, uint32_t b0, uint32_t b1) {
    asm volatile("mma.sync.aligned.m16n8k16.row.col.f32.f16.f16.f32 "
                 "{%0,%1,%2,%3}, {%4,%5,%6,%7}, {%8,%9}, {%0,%1,%2,%3};"
                 : "+f"(c[0]), "+f"(c[1]), "+f"(c[2]), "+f"(c[3])
                 : "r"(a[0]), "r"(a[1]), "r"(a[2]), "r"(a[3]), "r"(b0), "r"(b1));
}

// ---------------------------------------------------------------------------
// prep: build fp16 swizzled weight images once per launch.
//   g_w1: 192 rows(o) x 16 granules  [W0 | W1-W0 | root1]
//   g_w2: 128 rows(o) x 8 granules   [W0' | W1'-W0' | root2 | 0]
__global__ __launch_bounds__(256) void prep_kernel(
    const float* __restrict__ W1, const float* __restrict__ root1,
    const float* __restrict__ W2, const float* __restrict__ root2)
{
    int gi = blockIdx.x * 256 + threadIdx.x;    // 4096 granules
    if (gi < 192 * 16) {
        int o = gi >> 4, g = gi & 15;
        __half hv[8];
        #pragma unroll
        for (int j = 0; j < 8; j++) {
            int k = g * 8 + j;
            float val;
            if (o < 64)       val = __ldg(W1 + k * 64 + o);
            else if (o < 128) { int oo = o - 64;
                                val = __ldg(W1 + 128 * 64 + k * 64 + oo) - __ldg(W1 + k * 64 + oo); }
            else              val = __ldg(root1 + k * 64 + (o - 128));
            hv[j] = __float2half_rn(val);
        }
        *reinterpret_cast<int4*>(g_w1 + (o * 16 + (g ^ (o & 7))) * 8) =
            *reinterpret_cast<int4*>(hv);
    } else if (gi < 192 * 16 + 128 * 8) {
        int gi2 = gi - 192 * 16;
        int o = gi2 >> 3, g = gi2 & 7;
        __half hv[8];
        #pragma unroll
        for (int j = 0; j < 8; j++) {
            int k = g * 8 + j;
            float val;
            if (o < 40)       val = __ldg(W2 + k * 40 + o);
            else if (o < 80)  { int oo = o - 40;
                                val = __ldg(W2 + 64 * 40 + k * 40 + oo) - __ldg(W2 + k * 40 + oo); }
            else if (o < 120) val = __ldg(root2 + k * 40 + (o - 80));
            else              val = 0.f;
            hv[j] = __float2half_rn(val);
        }
        *reinterpret_cast<int4*>(g_w2 + (o * 8 + (g ^ (o & 7))) * 8) =
            *reinterpret_cast<int4*>(hv);
    }
}

// ---------------------------------------------------------------------------
// zero A1, A2, deg  (~21 MB)
__global__ __launch_bounds__(256) void zero_kernel() {
    size_t i = (size_t)blockIdx.x * blockDim.x + threadIdx.x;
    size_t stride = (size_t)gridDim.x * blockDim.x;
    float4 z = make_float4(0.f, 0.f, 0.f, 0.f);
    float4* a1 = reinterpret_cast<float4*>(g_A1);
    float4* a2 = reinterpret_cast<float4*>(g_A2);
    for (size_t j = i; j < (size_t)NPAD * 16; j += stride) a1[j] = z;
    for (size_t j = i; j < (size_t)NPAD * 10; j += stride) a2[j] = z;
    for (size_t j = i; j < NPAD; j += stride) g_deg[j] = 0.f;
}

// ---------------------------------------------------------------------------
// proj1 (HMMA): y[n, 0:192] = x[n] @ [W0 | W1-W0 | root1], fp16 in / fp32 acc.
// One block = 64 nodes x 192 outs. 8 warps: 4 along M x 2 along N(96).
// Weight tile copied (coalesced int4) from prebuilt g_w1 image.
__global__ __launch_bounds__(256) void proj1_kernel(const float* __restrict__ x)
{
    extern __shared__ __half hsmem[];
    __half* sA  = hsmem;              // 64*128 halves = 16 KB
    __half* sBt = hsmem + 64 * 128;   // 192*128 halves = 48 KB
    const int tid = threadIdx.x;
    const int nb  = blockIdx.x * 64;

    // sA: x rows fp32 -> fp16, swizzled
    for (int idx = tid; idx < 64 * 16; idx += 256) {
        int row = idx >> 4, g = idx & 15;
        int n = nb + row; if (n > NN - 1) n = NN - 1;
        const float4* xp = reinterpret_cast<const float4*>(x + (size_t)n * F1 + g * 8);
        float4 f0 = __ldg(xp);
        float4 f1 = __ldg(xp + 1);
        __half2 hh[4];
        hh[0] = __floats2half2_rn(f0.x, f0.y);
        hh[1] = __floats2half2_rn(f0.z, f0.w);
        hh[2] = __floats2half2_rn(f1.x, f1.y);
        hh[3] = __floats2half2_rn(f1.z, f1.w);
        *reinterpret_cast<int4*>(sA + (row * 16 + (g ^ (row & 7))) * 8) =
            *reinterpret_cast<int4*>(hh);
    }

    // sBt: straight copy of prebuilt image
    {
        const int4* src4 = reinterpret_cast<const int4*>(g_w1);
        int4* dst4 = reinterpret_cast<int4*>(sBt);
        #pragma unroll
        for (int r = 0; r < 12; r++) dst4[tid + r * 256] = __ldg(src4 + tid + r * 256);
    }
    __syncthreads();

    const int wid = tid >> 5;
    const int l   = tid & 31;
    const int m_base = (wid & 3) * 16;
    const int n_base = (wid >> 2) * 96;

    uint32_t sA_u  = (uint32_t)__cvta_generic_to_shared(sA);
    uint32_t sBt_u = (uint32_t)__cvta_generic_to_shared(sBt);

    const int rowA = m_base + (l & 7) + ((l >> 3) & 1) * 8;
    const int aGsel = (l >> 4) & 1;
    const int bRowOff = (l & 7) + ((l >> 4) & 1) * 8;
    const int bGsel = (l >> 3) & 1;

    float acc[12][4] = {};

    #pragma unroll
    for (int ks = 0; ks < 8; ks++) {
        int g2 = ks * 2;
        uint32_t a[4];
        {
            int gs = g2 + aGsel;
            uint32_t addr = sA_u + (uint32_t)((rowA * 16 + (gs ^ (rowA & 7))) * 16);
            ldsm_x4(addr, a[0], a[1], a[2], a[3]);
        }
        #pragma unroll
        for (int p = 0; p < 6; p++) {
            int nrow = n_base + p * 16 + bRowOff;
            int gs = g2 + bGsel;
            uint32_t addr = sBt_u + (uint32_t)((nrow * 16 + (gs ^ (nrow & 7))) * 16);
            uint32_t b0, b1, b2, b3;
            ldsm_x4(addr, b0, b1, b2, b3);
            mma16816(acc[2 * p],     a, b0, b1);
            mma16816(acc[2 * p + 1], a, b2, b3);
        }
    }

    const int r0 = nb + m_base + (l >> 2);
    const int r1 = r0 + 8;
    const int cofs = (l & 3) * 2;
    #pragma unroll
    for (int p = 0; p < 6; p++) {
        #pragma unroll
        for (int hh = 0; hh < 2; hh++) {
            int t2 = 2 * p + hh;
            int o = n_base + p * 16 + hh * 8 + cofs;
            if (o < 128) {
                *reinterpret_cast<__half2*>(g_y16 + (size_t)r0 * 128 + o) =
                    __floats2half2_rn(acc[t2][0], acc[t2][1]);
                *reinterpret_cast<__half2*>(g_y16 + (size_t)r1 * 128 + o) =
                    __floats2half2_rn(acc[t2][2], acc[t2][3]);
            } else {
                *reinterpret_cast<float2*>(g_yroot + (size_t)r0 * 64 + (o - 128)) =
                    make_float2(acc[t2][0], acc[t2][1]);
                *reinterpret_cast<float2*>(g_yroot + (size_t)r1 * 64 + (o - 128)) =
                    make_float2(acc[t2][2], acc[t2][3]);
            }
        }
    }
}

// ---------------------------------------------------------------------------
// scatter1: A1[dst] += y0[src] + v*yd[src]; deg[dst]++.  16 lanes/edge,
// 4 edges per thread.
__global__ __launch_bounds__(256) void scatter1_kernel(
    const int* __restrict__ src,
    const int* __restrict__ dst,
    const float* __restrict__ ea)
{
    int t = blockIdx.x * 256 + threadIdx.x;     // (NE/4)*16 threads
    int e0 = t >> 4;
    int lane = t & 15;

    #pragma unroll
    for (int u = 0; u < 4; u++) {
        int e = e0 + u * (NE / 4);
        int s = __ldg(src + e);
        int d = __ldg(dst + e);
        float v = __ldg(ea + e);
        const int2* yr = reinterpret_cast<const int2*>(g_y16 + (size_t)s * 128);
        int2 p0 = __ldg(yr + lane);
        int2 pd = __ldg(yr + 16 + lane);
        const __half2* h0 = reinterpret_cast<const __half2*>(&p0);
        const __half2* hd = reinterpret_cast<const __half2*>(&pd);
        float2 a0 = __half22float2(h0[0]), a1 = __half22float2(h0[1]);
        float2 d0 = __half22float2(hd[0]), d1 = __half22float2(hd[1]);
        red_add_v4(g_A1 + (size_t)d * 64 + lane * 4,
                   fmaf(v, d0.x, a0.x), fmaf(v, d0.y, a0.y),
                   fmaf(v, d1.x, a1.x), fmaf(v, d1.y, a1.y));
        if (lane == 0) atomicAdd(g_deg + d, 1.0f);
    }
}

// ---------------------------------------------------------------------------
// proj2 (HMMA, fused ELU): h = elu(A1/deg + yroot + bias1) -> fp16 SMEM,
// then z[n, 0:128] = h[n] @ [W0' | W1'-W0' | root2 | 0]  (m64 n128 k64).
__global__ __launch_bounds__(256) void proj2_kernel(const float* __restrict__ bias1)
{
    __shared__ __half sH[64 * 64];     // 8 KB
    __shared__ __half sBt[128 * 64];   // 16 KB
    const int tid = threadIdx.x;
    const int nb = blockIdx.x * 64;

    // weights: straight copy of prebuilt image
    {
        const int4* src4 = reinterpret_cast<const int4*>(g_w2);
        int4* dst4 = reinterpret_cast<int4*>(sBt);
        #pragma unroll
        for (int r = 0; r < 4; r++) dst4[tid + r * 256] = __ldg(src4 + tid + r * 256);
    }

    // h tile with fused ELU
    {
        int row = tid >> 2, gp = tid & 3;
        int n = nb + row;
        float inv = 1.0f / fmaxf(g_deg[n], 1.0f);
        #pragma unroll
        for (int gg = 0; gg < 2; gg++) {
            int g = gp * 2 + gg;
            const float4* ap = reinterpret_cast<const float4*>(g_A1 + (size_t)n * 64 + g * 8);
            const float4* yp = reinterpret_cast<const float4*>(g_yroot + (size_t)n * 64 + g * 8);
            const float4* bp = reinterpret_cast<const float4*>(bias1) + g * 2;
            float4 a0 = ap[0], a1 = ap[1];
            float4 y0 = yp[0], y1 = yp[1];
            float4 b0 = __ldg(bp), b1 = __ldg(bp + 1);
            float hv[8];
            hv[0] = a0.x * inv + y0.x + b0.x;
            hv[1] = a0.y * inv + y0.y + b0.y;
            hv[2] = a0.z * inv + y0.z + b0.z;
            hv[3] = a0.w * inv + y0.w + b0.w;
            hv[4] = a1.x * inv + y1.x + b1.x;
            hv[5] = a1.y * inv + y1.y + b1.y;
            hv[6] = a1.z * inv + y1.z + b1.z;
            hv[7] = a1.w * inv + y1.w + b1.w;
            __half2 hp[4];
            #pragma unroll
            for (int q = 0; q < 4; q++) {
                float u0 = hv[2 * q],     e0v = u0 > 0.f ? u0 : expm1f(u0);
                float u1 = hv[2 * q + 1], e1v = u1 > 0.f ? u1 : expm1f(u1);
                hp[q] = __floats2half2_rn(e0v, e1v);
            }
            *reinterpret_cast<int4*>(sH + (row * 8 + (g ^ (row & 7))) * 8) =
                *reinterpret_cast<int4*>(hp);
        }
    }
    __syncthreads();

    const int wid = tid >> 5;
    const int l   = tid & 31;
    const int m_base = (wid & 3) * 16;     // 0..48
    const int n_base = (wid >> 2) * 64;    // 0 or 64

    uint32_t sH_u  = (uint32_t)__cvta_generic_to_shared(sH);
    uint32_t sBt_u = (uint32_t)__cvta_generic_to_shared(sBt);

    const int rowA = m_base + (l & 7) + ((l >> 3) & 1) * 8;
    const int aGsel = (l >> 4) & 1;
    const int bRowOff = (l & 7) + ((l >> 4) & 1) * 8;
    const int bGsel = (l >> 3) & 1;

    float acc[8][4] = {};

    #pragma unroll
    for (int ks = 0; ks < 4; ks++) {
        int g2 = ks * 2;
        uint32_t a[4];
        {
            int gs = g2 + aGsel;
            uint32_t addr = sH_u + (uint32_t)((rowA * 8 + (gs ^ (rowA & 7))) * 16);
            ldsm_x4(addr, a[0], a[1], a[2], a[3]);
        }
        #pragma unroll
        for (int p = 0; p < 4; p++) {
            int nrow = n_base + p * 16 + bRowOff;
            int gs = g2 + bGsel;
            uint32_t addr = sBt_u + (uint32_t)((nrow * 8 + (gs ^ (nrow & 7))) * 16);
            uint32_t b0, b1, b2, b3;
            ldsm_x4(addr, b0, b1, b2, b3);
            mma16816(acc[2 * p],     a, b0, b1);
            mma16816(acc[2 * p + 1], a, b2, b3);
        }
    }

    const int r0 = nb + m_base + (l >> 2);
    const int r1 = r0 + 8;
    const int cofs = (l & 3) * 2;
    #pragma unroll
    for (int p = 0; p < 4; p++) {
        #pragma unroll
        for (int hh = 0; hh < 2; hh++) {
            int t2 = 2 * p + hh;
            int o = n_base + p * 16 + hh * 8 + cofs;
            if (o < 80) {
                *reinterpret_cast<__half2*>(g_z16 + (size_t)r0 * 80 + o) =
                    __floats2half2_rn(acc[t2][0], acc[t2][1]);
                *reinterpret_cast<__half2*>(g_z16 + (size_t)r1 * 80 + o) =
                    __floats2half2_rn(acc[t2][2], acc[t2][3]);
            } else if (o < 120) {
                *reinterpret_cast<float2*>(g_zroot + (size_t)r0 * 40 + (o - 80)) =
                    make_float2(acc[t2][0], acc[t2][1]);
                *reinterpret_cast<float2*>(g_zroot + (size_t)r1 * 40 + (o - 80)) =
                    make_float2(acc[t2][2], acc[t2][3]);
            }
        }
    }
}

// ---------------------------------------------------------------------------
// scatter2: A2[dst] += z0[src] + v*zd[src].  5 lanes/edge, 4 edges/thread.
__global__ __launch_bounds__(256) void scatter2_kernel(
    const int* __restrict__ src,
    const int* __restrict__ dst,
    const float* __restrict__ ea)
{
    unsigned t = blockIdx.x * 256 + threadIdx.x;
    if (t >= (NE / 4) * 5) return;
    unsigned e0 = t / 5u;
    unsigned lane = t - e0 * 5u;

    #pragma unroll
    for (int u = 0; u < 4; u++) {
        unsigned e = e0 + u * (NE / 4);
        int s = __ldg(src + e), d = __ldg(dst + e);
        float v = __ldg(ea + e);
        const int4* zr = reinterpret_cast<const int4*>(g_z16 + (size_t)s * 80);
        int4 p0 = __ldg(zr + lane);
        int4 pd = __ldg(zr + 5 + lane);
        float a0[8], ad[8];
        h8_to_f8(p0, a0); h8_to_f8(pd, ad);
        float m[8];
        #pragma unroll
        for (int q = 0; q < 8; q++) m[q] = fmaf(v, ad[q], a0[q]);
        float* Ap = g_A2 + (size_t)d * 40 + lane * 8;
        red_add_v4(Ap,     m[0], m[1], m[2], m[3]);
        red_add_v4(Ap + 4, m[4], m[5], m[6], m[7]);
    }
}

// ---------------------------------------------------------------------------
// final: out = A2/deg + zroot + bias2
__global__ __launch_bounds__(256) void final_kernel(
    const float* __restrict__ bias2, float* __restrict__ out)
{
    unsigned t = blockIdx.x * 256 + threadIdx.x;   // NN*10 threads
    if (t >= NN * 10) return;
    unsigned n = t / 10u;
    unsigned l = t - n * 10u;
    float inv = 1.0f / fmaxf(g_deg[n], 1.0f);
    float4 a  = *reinterpret_cast<const float4*>(g_A2 + (size_t)n * 40 + l * 4);
    float4 zr = *reinterpret_cast<const float4*>(g_zroot + (size_t)n * 40 + l * 4);
    float4 b  = __ldg(reinterpret_cast<const float4*>(bias2) + l);
    float4 o;
    o.x = a.x * inv + zr.x + b.x;
    o.y = a.y * inv + zr.y + b.y;
    o.z = a.z * inv + zr.z + b.z;
    o.w = a.w * inv + zr.w + b.w;
    *reinterpret_cast<float4*>(out + (size_t)n * 40 + l * 4) = o;
}

// ---------------------------------------------------------------------------
extern "C" void kernel_launch(void* const* d_in, const int* in_sizes, int n_in,
                              void* d_out, int out_size)
{
    const float* x     = (const float*)d_in[0];
    const int*   eidx  = (const int*)  d_in[1];
    const float* ea    = (const float*)d_in[2];
    const float* W1    = (const float*)d_in[3];
    const float* root1 = (const float*)d_in[4];
    const float* bias1 = (const float*)d_in[5];
    const float* W2    = (const float*)d_in[6];
    const float* root2 = (const float*)d_in[7];
    const float* bias2 = (const float*)d_in[8];
    float* out = (float*)d_out;

    const int* src = eidx;
    const int* dst = eidx + NE;

    const int p1_smem = 256 * 128 * (int)sizeof(__half);   // 65536 B
    cudaFuncSetAttribute(proj1_kernel, cudaFuncAttributeMaxDynamicSharedMemorySize, p1_smem);

    prep_kernel<<<16, 256>>>(W1, root1, W2, root2);
    zero_kernel<<<2048, 256>>>();
    proj1_kernel<<<NPAD / 64, 256, p1_smem>>>(x);
    scatter1_kernel<<<((NE / 4) * 16) / 256, 256>>>(src, dst, ea);
    proj2_kernel<<<NPAD / 64, 256>>>(bias1);
    scatter2_kernel<<<((NE / 4) * 5 + 255) / 256, 256>>>(src, dst, ea);
    final_kernel<<<(NN * 10 + 255) / 256, 256>>>(bias2, out);
}